// round 2
// baseline (speedup 1.0000x reference)
#include <cuda_runtime.h>
#include <math.h>

#define BB 4
#define TT 2048
#define DM 2048
#define NH 16
#define DH 128

// ---- scratch (allocation-free: __device__ globals) ----
__device__ float g_q[(size_t)BB * TT * DM];    // 64 MB
__device__ float g_k[(size_t)BB * TT * DH];    // 4 MB
__device__ float g_v[(size_t)BB * TT * DH];    // 4 MB
__device__ float g_ctx[(size_t)BB * TT * DM];  // 64 MB

// Destination selector so kernel_launch never needs cudaGetSymbolAddress.
// 0 -> g_q, 1 -> g_k, 2 -> g_v, 3 -> external pointer (Cext)
__device__ __forceinline__ float* dst_ptr(int sel, float* Cext) {
    switch (sel) {
        case 0: return g_q;
        case 1: return g_k;
        case 2: return g_v;
        default: return Cext;
    }
}
// Source selector: 0 -> external (x), 1 -> g_ctx
__device__ __forceinline__ const float* src_ptr(int sel, const float* Aext) {
    return sel == 1 ? g_ctx : Aext;
}

// ============================================================
// Tiled SGEMM with bias: C[M,N] = A[M,K] @ B[K,N] + bias[N]
// 128x128 block tile, BK=8, 256 threads, 8x8 per thread.
// Requires M%128==0, N%128==0, K%8==0, N%4==0 (all true here).
// ============================================================
__global__ __launch_bounds__(256) void sgemm_bias_kernel(
    const float* __restrict__ Aext, const float* __restrict__ B,
    const float* __restrict__ bias, float* __restrict__ Cext,
    int M, int N, int K, int srcSel, int dstSel)
{
    const float* A = src_ptr(srcSel, Aext);
    float* C = dst_ptr(dstSel, Cext);

    __shared__ float As[8][132];   // transposed A tile, padded (conflict-free)
    __shared__ float Bs[8][128];

    const int tid = threadIdx.x;
    const int tx = tid & 15;
    const int ty = tid >> 4;
    const int rowBase = blockIdx.y * 128;
    const int colBase = blockIdx.x * 128;

    const int aRow = tid >> 1;          // 0..127
    const int aCol = (tid & 1) * 4;     // 0 or 4
    const int bRow = tid >> 5;          // 0..7
    const int bCol = (tid & 31) * 4;    // 0..124

    const float* Aptr = A + (size_t)(rowBase + aRow) * K + aCol;
    const float* Bptr = B + (size_t)bRow * N + colBase + bCol;

    float acc[8][8];
#pragma unroll
    for (int i = 0; i < 8; i++)
#pragma unroll
        for (int j = 0; j < 8; j++) acc[i][j] = 0.f;

    for (int k0 = 0; k0 < K; k0 += 8) {
        const float4 a4 = *(const float4*)(Aptr + k0);
        const float4 b4 = *(const float4*)(Bptr + (size_t)k0 * N);
        As[aCol + 0][aRow] = a4.x;
        As[aCol + 1][aRow] = a4.y;
        As[aCol + 2][aRow] = a4.z;
        As[aCol + 3][aRow] = a4.w;
        *(float4*)&Bs[bRow][bCol] = b4;
        __syncthreads();

#pragma unroll
        for (int kk = 0; kk < 8; kk++) {
            float a[8], b[8];
            *(float4*)&a[0] = *(const float4*)&As[kk][ty * 8];
            *(float4*)&a[4] = *(const float4*)&As[kk][ty * 8 + 4];
            *(float4*)&b[0] = *(const float4*)&Bs[kk][tx * 8];
            *(float4*)&b[4] = *(const float4*)&Bs[kk][tx * 8 + 4];
#pragma unroll
            for (int i = 0; i < 8; i++)
#pragma unroll
                for (int j = 0; j < 8; j++)
                    acc[i][j] = fmaf(a[i], b[j], acc[i][j]);
        }
        __syncthreads();
    }

#pragma unroll
    for (int i = 0; i < 8; i++) {
        const size_t r = (size_t)rowBase + ty * 8 + i;
#pragma unroll
        for (int j = 0; j < 8; j += 4) {
            const int c = colBase + tx * 8 + j;
            float4 o;
            o.x = acc[i][j + 0] + bias[c + 0];
            o.y = acc[i][j + 1] + bias[c + 1];
            o.z = acc[i][j + 2] + bias[c + 2];
            o.w = acc[i][j + 3] + bias[c + 3];
            *(float4*)(C + r * N + c) = o;
        }
    }
}

// ============================================================
// Flash-attention (causal, MQA): per (qb, h, b) CTA.
// 64 query rows x 64 key cols per tile, Dh=128.
// 256 threads: 4 threads per query row (quad), each owns 32 out dims.
// Online softmax; O accumulated in registers.
// Reads g_q/g_k/g_v, writes g_ctx (device globals, no pointers needed).
// ============================================================
#define QS 132   // padded smem row stride (floats)

__global__ __launch_bounds__(256) void mqa_attn_kernel()
{
    extern __shared__ float sh[];
    float* Qs = sh;                   // 64*132
    float* Ks = sh + 64 * QS;         // 64*132
    float* Vs = sh + 2 * 64 * QS;     // 64*132
    float* Ps = sh + 3 * 64 * QS;     // 64*68

    const int qb = blockIdx.x;
    const int h  = blockIdx.y;
    const int b  = blockIdx.z;
    const int tid = threadIdx.x;
    const int r = tid >> 2;           // query row within tile (0..63)
    const int quad = tid & 3;         // sub-lane within row
    const int t = qb * 64 + r;        // global query index

    // Load Q tile (64 x 128) once
    for (int i = tid; i < 64 * 32; i += 256) {
        const int row = i >> 5;
        const int c4 = (i & 31) << 2;
        *(float4*)(Qs + row * QS + c4) =
            *(const float4*)(g_q + (size_t)(b * TT + qb * 64 + row) * DM + h * DH + c4);
    }

    float O[32];
#pragma unroll
    for (int u = 0; u < 32; u++) O[u] = 0.f;
    float m_i = -1e30f, l_i = 0.f;
    const float scale = 0.08838834764831845f;  // 1/sqrt(128)

    for (int kb = 0; kb <= qb; kb++) {
        __syncthreads();  // protect Ks/Vs/Ps reuse across iterations (and Q load)
        // Load K & V tiles (64 x 128 each), coalesced float4
        for (int i = tid; i < 64 * 32; i += 256) {
            const int row = i >> 5;
            const int c4 = (i & 31) << 2;
            const size_t g = (size_t)(b * TT + kb * 64 + row) * DH + c4;
            *(float4*)(Ks + row * QS + c4) = *(const float4*)(g_k + g);
            *(float4*)(Vs + row * QS + c4) = *(const float4*)(g_v + g);
        }
        __syncthreads();

        // S[r][c] for c = quad + 4*j  (interleaved -> conflict-free K reads)
        float acc[16];
#pragma unroll
        for (int j = 0; j < 16; j++) acc[j] = 0.f;
#pragma unroll 4
        for (int d4 = 0; d4 < 32; d4++) {
            const float4 q4 = *(const float4*)(Qs + r * QS + d4 * 4);
#pragma unroll
            for (int j = 0; j < 16; j++) {
                const float4 k4 = *(const float4*)(Ks + (quad + 4 * j) * QS + d4 * 4);
                acc[j] = fmaf(q4.x, k4.x,
                         fmaf(q4.y, k4.y,
                         fmaf(q4.z, k4.z,
                         fmaf(q4.w, k4.w, acc[j]))));
            }
        }

        // scale + causal mask + local max
        float mloc = -1e30f;
        const int sbase = kb * 64 + quad;
#pragma unroll
        for (int j = 0; j < 16; j++) {
            float sv = acc[j] * scale;
            if (sbase + 4 * j > t) sv = -1e30f;
            acc[j] = sv;
            mloc = fmaxf(mloc, sv);
        }
        // quad-reduce max (the 4 threads of a row are adjacent lanes)
        mloc = fmaxf(mloc, __shfl_xor_sync(0xffffffffu, mloc, 1));
        mloc = fmaxf(mloc, __shfl_xor_sync(0xffffffffu, mloc, 2));
        const float m_new = fmaxf(m_i, mloc);
        const float alpha = __expf(m_i - m_new);

        float psum = 0.f;
#pragma unroll
        for (int j = 0; j < 16; j++) {
            const float p = __expf(acc[j] - m_new);
            psum += p;
            Ps[r * 68 + quad + 4 * j] = p;
        }
        psum += __shfl_xor_sync(0xffffffffu, psum, 1);
        psum += __shfl_xor_sync(0xffffffffu, psum, 2);
        l_i = l_i * alpha + psum;
        m_i = m_new;

#pragma unroll
        for (int u = 0; u < 32; u++) O[u] *= alpha;
        __syncwarp();  // Ps produced/consumed within the same warp

        // O[r][quad*32+u] += sum_c P[r][c] * V[c][quad*32+u]
        // c staggered by 17*quad -> distinct bank groups for the 4 quads
#pragma unroll 2
        for (int cc = 0; cc < 64; cc++) {
            const int c = (cc + 17 * quad) & 63;
            const float p = Ps[r * 68 + c];
            const float* vrow = Vs + c * QS + quad * 32;
#pragma unroll
            for (int u4 = 0; u4 < 8; u4++) {
                const float4 v4 = *(const float4*)(vrow + u4 * 4);
                O[u4 * 4 + 0] = fmaf(p, v4.x, O[u4 * 4 + 0]);
                O[u4 * 4 + 1] = fmaf(p, v4.y, O[u4 * 4 + 1]);
                O[u4 * 4 + 2] = fmaf(p, v4.z, O[u4 * 4 + 2]);
                O[u4 * 4 + 3] = fmaf(p, v4.w, O[u4 * 4 + 3]);
            }
        }
    }

    const float inv = 1.0f / l_i;
    float* dst = g_ctx + (size_t)(b * TT + t) * DM + h * DH + quad * 32;
#pragma unroll
    for (int u4 = 0; u4 < 8; u4++) {
        float4 o;
        o.x = O[u4 * 4 + 0] * inv;
        o.y = O[u4 * 4 + 1] * inv;
        o.z = O[u4 * 4 + 2] * inv;
        o.w = O[u4 * 4 + 3] * inv;
        *(float4*)(dst + u4 * 4) = o;
    }
}

// ============================================================
// Launch
// ============================================================
extern "C" void kernel_launch(void* const* d_in, const int* in_sizes, int n_in,
                              void* d_out, int out_size)
{
    // metadata order: x, mask, Wq, bq, Wk, bk, Wv, bv, Wo, bo
    const float* x  = (const float*)d_in[0];
    // d_in[1] = mask (pure causal triu(-inf); handled analytically)
    const float* Wq = (const float*)d_in[2];
    const float* bq = (const float*)d_in[3];
    const float* Wk = (const float*)d_in[4];
    const float* bk = (const float*)d_in[5];
    const float* Wv = (const float*)d_in[6];
    const float* bv = (const float*)d_in[7];
    const float* Wo = (const float*)d_in[8];
    const float* bo = (const float*)d_in[9];
    float* out = (float*)d_out;

    const int M = BB * TT;  // 8192
    dim3 blk(256);

    // Projections: src x (sel 0), dst g_q/g_k/g_v (sel 0/1/2)
    sgemm_bias_kernel<<<dim3(DM / 128, M / 128), blk>>>(x, Wq, bq, nullptr, M, DM, DM, 0, 0);
    sgemm_bias_kernel<<<dim3(DH / 128, M / 128), blk>>>(x, Wk, bk, nullptr, M, DH, DM, 0, 1);
    sgemm_bias_kernel<<<dim3(DH / 128, M / 128), blk>>>(x, Wv, bv, nullptr, M, DH, DM, 0, 2);

    // Attention (reads g_q/g_k/g_v, writes g_ctx)
    const int smem = (3 * 64 * QS + 64 * 68) * (int)sizeof(float);  // 118784 B
    cudaFuncSetAttribute(mqa_attn_kernel,
                         cudaFuncAttributeMaxDynamicSharedMemorySize, smem);
    mqa_attn_kernel<<<dim3(TT / 64, NH, BB), blk, smem>>>();

    // Output projection: src g_ctx (sel 1), dst external out (sel 3)
    sgemm_bias_kernel<<<dim3(DM / 128, M / 128), blk>>>(nullptr, Wo, bo, out, M, DM, DM, 1, 3);
}

// round 3
// speedup vs baseline: 1.0026x; 1.0026x over previous
#include <cuda_runtime.h>
#include <math.h>

#define BB 4
#define TT 2048
#define DM 2048
#define NH 16
#define DH 128

// ---- scratch (allocation-free: __device__ globals) ----
__device__ float g_q[(size_t)BB * TT * DM];    // 64 MB
__device__ float g_k[(size_t)BB * TT * DH];    // 4 MB
__device__ float g_v[(size_t)BB * TT * DH];    // 4 MB
__device__ float g_ctx[(size_t)BB * TT * DM];  // 64 MB

// Destination selector so kernel_launch never needs cudaGetSymbolAddress.
// 0 -> g_q, 1 -> g_k, 2 -> g_v, 3 -> external pointer (Cext)
__device__ __forceinline__ float* dst_ptr(int sel, float* Cext) {
    switch (sel) {
        case 0: return g_q;
        case 1: return g_k;
        case 2: return g_v;
        default: return Cext;
    }
}
// Source selector: 0 -> external (x), 1 -> g_ctx
__device__ __forceinline__ const float* src_ptr(int sel, const float* Aext) {
    return sel == 1 ? g_ctx : Aext;
}

// ============================================================
// Tiled SGEMM with bias: C[M,N] = A[M,K] @ B[K,N] + bias[N]
// 128x128 block tile, BK=8, 256 threads, 8x8 per thread.
// Requires M%128==0, N%128==0, K%8==0, N%4==0 (all true here).
// ============================================================
__global__ __launch_bounds__(256) void sgemm_bias_kernel(
    const float* __restrict__ Aext, const float* __restrict__ B,
    const float* __restrict__ bias, float* __restrict__ Cext,
    int M, int N, int K, int srcSel, int dstSel)
{
    const float* A = src_ptr(srcSel, Aext);
    float* C = dst_ptr(dstSel, Cext);

    __shared__ float As[8][132];   // transposed A tile, padded (conflict-free)
    __shared__ float Bs[8][128];

    const int tid = threadIdx.x;
    const int tx = tid & 15;
    const int ty = tid >> 4;
    const int rowBase = blockIdx.y * 128;
    const int colBase = blockIdx.x * 128;

    const int aRow = tid >> 1;          // 0..127
    const int aCol = (tid & 1) * 4;     // 0 or 4
    const int bRow = tid >> 5;          // 0..7
    const int bCol = (tid & 31) * 4;    // 0..124

    const float* Aptr = A + (size_t)(rowBase + aRow) * K + aCol;
    const float* Bptr = B + (size_t)bRow * N + colBase + bCol;

    float acc[8][8];
#pragma unroll
    for (int i = 0; i < 8; i++)
#pragma unroll
        for (int j = 0; j < 8; j++) acc[i][j] = 0.f;

    for (int k0 = 0; k0 < K; k0 += 8) {
        const float4 a4 = *(const float4*)(Aptr + k0);
        const float4 b4 = *(const float4*)(Bptr + (size_t)k0 * N);
        As[aCol + 0][aRow] = a4.x;
        As[aCol + 1][aRow] = a4.y;
        As[aCol + 2][aRow] = a4.z;
        As[aCol + 3][aRow] = a4.w;
        *(float4*)&Bs[bRow][bCol] = b4;
        __syncthreads();

#pragma unroll
        for (int kk = 0; kk < 8; kk++) {
            float a[8], b[8];
            *(float4*)&a[0] = *(const float4*)&As[kk][ty * 8];
            *(float4*)&a[4] = *(const float4*)&As[kk][ty * 8 + 4];
            *(float4*)&b[0] = *(const float4*)&Bs[kk][tx * 8];
            *(float4*)&b[4] = *(const float4*)&Bs[kk][tx * 8 + 4];
#pragma unroll
            for (int i = 0; i < 8; i++)
#pragma unroll
                for (int j = 0; j < 8; j++)
                    acc[i][j] = fmaf(a[i], b[j], acc[i][j]);
        }
        __syncthreads();
    }

#pragma unroll
    for (int i = 0; i < 8; i++) {
        const size_t r = (size_t)rowBase + ty * 8 + i;
#pragma unroll
        for (int j = 0; j < 8; j += 4) {
            const int c = colBase + tx * 8 + j;
            float4 o;
            o.x = acc[i][j + 0] + bias[c + 0];
            o.y = acc[i][j + 1] + bias[c + 1];
            o.z = acc[i][j + 2] + bias[c + 2];
            o.w = acc[i][j + 3] + bias[c + 3];
            *(float4*)(C + r * N + c) = o;
        }
    }
}

// ============================================================
// Flash-attention (causal, MQA): per (qb, h, b) CTA.
// 64 query rows x 64 key cols per tile, Dh=128.
// 256 threads: 4 threads per query row (quad), each owns 32 out dims.
// Online softmax; O accumulated in registers.
// Reads g_q/g_k/g_v, writes g_ctx (device globals, no pointers needed).
// ============================================================
#define QS 132   // padded smem row stride (floats)

__global__ __launch_bounds__(256) void mqa_attn_kernel()
{
    extern __shared__ float sh[];
    float* Qs = sh;                   // 64*132
    float* Ks = sh + 64 * QS;         // 64*132
    float* Vs = sh + 2 * 64 * QS;     // 64*132
    float* Ps = sh + 3 * 64 * QS;     // 64*68

    const int qb = blockIdx.x;
    const int h  = blockIdx.y;
    const int b  = blockIdx.z;
    const int tid = threadIdx.x;
    const int r = tid >> 2;           // query row within tile (0..63)
    const int quad = tid & 3;         // sub-lane within row
    const int t = qb * 64 + r;        // global query index

    // Load Q tile (64 x 128) once
    for (int i = tid; i < 64 * 32; i += 256) {
        const int row = i >> 5;
        const int c4 = (i & 31) << 2;
        *(float4*)(Qs + row * QS + c4) =
            *(const float4*)(g_q + (size_t)(b * TT + qb * 64 + row) * DM + h * DH + c4);
    }

    float O[32];
#pragma unroll
    for (int u = 0; u < 32; u++) O[u] = 0.f;
    float m_i = -1e30f, l_i = 0.f;
    const float scale = 0.08838834764831845f;  // 1/sqrt(128)

    for (int kb = 0; kb <= qb; kb++) {
        __syncthreads();  // protect Ks/Vs/Ps reuse across iterations (and Q load)
        // Load K & V tiles (64 x 128 each), coalesced float4
        for (int i = tid; i < 64 * 32; i += 256) {
            const int row = i >> 5;
            const int c4 = (i & 31) << 2;
            const size_t g = (size_t)(b * TT + kb * 64 + row) * DH + c4;
            *(float4*)(Ks + row * QS + c4) = *(const float4*)(g_k + g);
            *(float4*)(Vs + row * QS + c4) = *(const float4*)(g_v + g);
        }
        __syncthreads();

        // S[r][c] for c = quad + 4*j  (interleaved -> conflict-free K reads)
        float acc[16];
#pragma unroll
        for (int j = 0; j < 16; j++) acc[j] = 0.f;
#pragma unroll 4
        for (int d4 = 0; d4 < 32; d4++) {
            const float4 q4 = *(const float4*)(Qs + r * QS + d4 * 4);
#pragma unroll
            for (int j = 0; j < 16; j++) {
                const float4 k4 = *(const float4*)(Ks + (quad + 4 * j) * QS + d4 * 4);
                acc[j] = fmaf(q4.x, k4.x,
                         fmaf(q4.y, k4.y,
                         fmaf(q4.z, k4.z,
                         fmaf(q4.w, k4.w, acc[j]))));
            }
        }

        // scale + causal mask + local max
        float mloc = -1e30f;
        const int sbase = kb * 64 + quad;
#pragma unroll
        for (int j = 0; j < 16; j++) {
            float sv = acc[j] * scale;
            if (sbase + 4 * j > t) sv = -1e30f;
            acc[j] = sv;
            mloc = fmaxf(mloc, sv);
        }
        // quad-reduce max (the 4 threads of a row are adjacent lanes)
        mloc = fmaxf(mloc, __shfl_xor_sync(0xffffffffu, mloc, 1));
        mloc = fmaxf(mloc, __shfl_xor_sync(0xffffffffu, mloc, 2));
        const float m_new = fmaxf(m_i, mloc);
        const float alpha = __expf(m_i - m_new);

        float psum = 0.f;
#pragma unroll
        for (int j = 0; j < 16; j++) {
            const float p = __expf(acc[j] - m_new);
            psum += p;
            Ps[r * 68 + quad + 4 * j] = p;
        }
        psum += __shfl_xor_sync(0xffffffffu, psum, 1);
        psum += __shfl_xor_sync(0xffffffffu, psum, 2);
        l_i = l_i * alpha + psum;
        m_i = m_new;

#pragma unroll
        for (int u = 0; u < 32; u++) O[u] *= alpha;
        __syncwarp();  // Ps produced/consumed within the same warp

        // O[r][quad*32+u] += sum_c P[r][c] * V[c][quad*32+u]
        // c staggered by 17*quad -> distinct bank groups for the 4 quads
#pragma unroll 2
        for (int cc = 0; cc < 64; cc++) {
            const int c = (cc + 17 * quad) & 63;
            const float p = Ps[r * 68 + c];
            const float* vrow = Vs + c * QS + quad * 32;
#pragma unroll
            for (int u4 = 0; u4 < 8; u4++) {
                const float4 v4 = *(const float4*)(vrow + u4 * 4);
                O[u4 * 4 + 0] = fmaf(p, v4.x, O[u4 * 4 + 0]);
                O[u4 * 4 + 1] = fmaf(p, v4.y, O[u4 * 4 + 1]);
                O[u4 * 4 + 2] = fmaf(p, v4.z, O[u4 * 4 + 2]);
                O[u4 * 4 + 3] = fmaf(p, v4.w, O[u4 * 4 + 3]);
            }
        }
    }

    const float inv = 1.0f / l_i;
    float* dst = g_ctx + (size_t)(b * TT + t) * DM + h * DH + quad * 32;
#pragma unroll
    for (int u4 = 0; u4 < 8; u4++) {
        float4 o;
        o.x = O[u4 * 4 + 0] * inv;
        o.y = O[u4 * 4 + 1] * inv;
        o.z = O[u4 * 4 + 2] * inv;
        o.w = O[u4 * 4 + 3] * inv;
        *(float4*)(dst + u4 * 4) = o;
    }
}

// ============================================================
// Launch
// ============================================================
extern "C" void kernel_launch(void* const* d_in, const int* in_sizes, int n_in,
                              void* d_out, int out_size)
{
    // metadata order: x, mask, Wq, bq, Wk, bk, Wv, bv, Wo, bo
    const float* x  = (const float*)d_in[0];
    // d_in[1] = mask (pure causal triu(-inf); handled analytically)
    const float* Wq = (const float*)d_in[2];
    const float* bq = (const float*)d_in[3];
    const float* Wk = (const float*)d_in[4];
    const float* bk = (const float*)d_in[5];
    const float* Wv = (const float*)d_in[6];
    const float* bv = (const float*)d_in[7];
    const float* Wo = (const float*)d_in[8];
    const float* bo = (const float*)d_in[9];
    float* out = (float*)d_out;

    const int M = BB * TT;  // 8192
    dim3 blk(256);

    // Projections: src x (sel 0), dst g_q/g_k/g_v (sel 0/1/2)
    sgemm_bias_kernel<<<dim3(DM / 128, M / 128), blk>>>(x, Wq, bq, nullptr, M, DM, DM, 0, 0);
    sgemm_bias_kernel<<<dim3(DH / 128, M / 128), blk>>>(x, Wk, bk, nullptr, M, DH, DM, 0, 1);
    sgemm_bias_kernel<<<dim3(DH / 128, M / 128), blk>>>(x, Wv, bv, nullptr, M, DH, DM, 0, 2);

    // Attention (reads g_q/g_k/g_v, writes g_ctx)
    const int smem = (3 * 64 * QS + 64 * 68) * (int)sizeof(float);  // 118784 B
    cudaFuncSetAttribute(mqa_attn_kernel,
                         cudaFuncAttributeMaxDynamicSharedMemorySize, smem);
    mqa_attn_kernel<<<dim3(TT / 64, NH, BB), blk, smem>>>();

    // Output projection: src g_ctx (sel 1), dst external out (sel 3)
    sgemm_bias_kernel<<<dim3(DM / 128, M / 128), blk>>>(nullptr, Wo, bo, out, M, DM, DM, 1, 3);
}

// round 5
// speedup vs baseline: 1.3491x; 1.3455x over previous
#include <cuda_runtime.h>
#include <cuda_bf16.h>
#include <cstdint>

#define BBAT 4
#define TT 2048
#define DM 2048
#define NH 16
#define DH 128
#define MROWS (BBAT * TT)

// ---- scratch ----
__device__ float g_q[(size_t)MROWS * DM];
__device__ float g_k[(size_t)MROWS * DH];
__device__ float g_v[(size_t)MROWS * DH];
__device__ float g_ctx[(size_t)MROWS * DM];
__device__ __nv_bfloat16 g_xhi[(size_t)MROWS * DM], g_xlo[(size_t)MROWS * DM];
__device__ __nv_bfloat16 g_chi[(size_t)MROWS * DM], g_clo[(size_t)MROWS * DM];
__device__ __nv_bfloat16 g_wqhi[(size_t)DM * DM], g_wqlo[(size_t)DM * DM];
__device__ __nv_bfloat16 g_wkhi[(size_t)DH * DM], g_wklo[(size_t)DH * DM];
__device__ __nv_bfloat16 g_wvhi[(size_t)DH * DM], g_wvlo[(size_t)DH * DM];
__device__ __nv_bfloat16 g_wohi[(size_t)DM * DM], g_wolo[(size_t)DM * DM];

// ---- PTX helpers (sm_80+ classic tensor path; NO tcgen05 on sm_100 base) ----
__device__ __forceinline__ uint32_t smem_u32(const void* p) {
    uint32_t a;
    asm("{ .reg .u64 t; cvta.to.shared.u64 t, %1; cvt.u32.u64 %0, t; }" : "=r"(a) : "l"(p));
    return a;
}
#define CP16(s, g) \
    asm volatile("cp.async.cg.shared.global [%0], [%1], 16;" :: "r"(s), "l"(g))
#define CP_COMMIT() asm volatile("cp.async.commit_group;" ::: "memory")
#define CP_WAIT1() asm volatile("cp.async.wait_group 1;" ::: "memory")
#define CP_WAIT0() asm volatile("cp.async.wait_group 0;" ::: "memory")

__device__ __forceinline__ void ldsm_x4(uint32_t& r0, uint32_t& r1, uint32_t& r2,
                                        uint32_t& r3, uint32_t addr) {
    asm volatile("ldmatrix.sync.aligned.m8n8.x4.shared.b16 {%0,%1,%2,%3}, [%4];"
                 : "=r"(r0), "=r"(r1), "=r"(r2), "=r"(r3) : "r"(addr));
}
__device__ __forceinline__ void mma16816(float* c, const uint32_t* a, const uint32_t* b) {
    asm volatile("mma.sync.aligned.m16n8k16.row.col.f32.bf16.bf16.f32 "
                 "{%0,%1,%2,%3}, {%4,%5,%6,%7}, {%8,%9}, {%0,%1,%2,%3};"
                 : "+f"(c[0]), "+f"(c[1]), "+f"(c[2]), "+f"(c[3])
                 : "r"(a[0]), "r"(a[1]), "r"(a[2]), "r"(a[3]), "r"(b[0]), "r"(b[1]));
}

// ---- fp32 -> bf16 hi/lo ----
__device__ __forceinline__ void split1(float v, __nv_bfloat16& h, __nv_bfloat16& l) {
    h = __float2bfloat16(v);
    l = __float2bfloat16(v - __bfloat162float(h));
}
__device__ __forceinline__ uint32_t pk2(__nv_bfloat16 a, __nv_bfloat16 b) {
    return (uint32_t)__bfloat16_as_ushort(a) | ((uint32_t)__bfloat16_as_ushort(b) << 16);
}

__global__ __launch_bounds__(256) void split_kernel(const float* __restrict__ ext,
                                                    int srcSel, int n4) {
    const float* src = srcSel ? g_ctx : ext;
    __nv_bfloat16* hi = srcSel ? g_chi : g_xhi;
    __nv_bfloat16* lo = srcSel ? g_clo : g_xlo;
    for (int i = blockIdx.x * blockDim.x + threadIdx.x; i < n4; i += gridDim.x * blockDim.x) {
        float4 v = ((const float4*)src)[i];
        __nv_bfloat16 h0, h1, h2, h3, l0, l1, l2, l3;
        split1(v.x, h0, l0); split1(v.y, h1, l1); split1(v.z, h2, l2); split1(v.w, h3, l3);
        uint2 H, L;
        H.x = pk2(h0, h1); H.y = pk2(h2, h3);
        L.x = pk2(l0, l1); L.y = pk2(l2, l3);
        ((uint2*)hi)[i] = H;
        ((uint2*)lo)[i] = L;
    }
}

// transpose W[K,N] -> Wt[N,K] bf16 hi/lo
__global__ __launch_bounds__(256) void tsplit_kernel(const float* __restrict__ W,
                                                     int wsel, int Kd, int Nd) {
    __nv_bfloat16 *hi, *lo;
    if (wsel == 0)      { hi = g_wqhi; lo = g_wqlo; }
    else if (wsel == 1) { hi = g_wkhi; lo = g_wklo; }
    else if (wsel == 2) { hi = g_wvhi; lo = g_wvlo; }
    else                { hi = g_wohi; lo = g_wolo; }
    __shared__ float t[32][33];
    const int nb = blockIdx.x * 32, kb = blockIdx.y * 32;
    const int tx = threadIdx.x & 31, ty = threadIdx.x >> 5;
#pragma unroll
    for (int i = 0; i < 4; i++)
        t[ty + 8 * i][tx] = W[(size_t)(kb + ty + 8 * i) * Nd + nb + tx];
    __syncthreads();
#pragma unroll
    for (int i = 0; i < 4; i++) {
        const int nrow = ty + 8 * i;
        __nv_bfloat16 h, l;
        split1(t[tx][nrow], h, l);
        const size_t o = (size_t)(nb + nrow) * Kd + kb + tx;
        hi[o] = h; lo[o] = l;
    }
}

// ============================================================
// mma.sync bf16x3 GEMM: C[.,N] = A[.,2048] @ Wt[N,2048]^T + bias
// 128x128 tile, BK=32, 256 thr (4x2 warps, 32x64 each), cp.async x2 stages.
// smem stage (40960B): Ahi@0  Alo@10240  Bhi@20480  Blo@30720
// rows: 128 x 80B (32 bf16 + 8 pad) -> conflict-free ldmatrix.
// ============================================================
#define STG 40960
#define OAH 0
#define OAL 10240
#define OBH 20480
#define OBL 30720

__global__ __launch_bounds__(256) void tc_gemm(const float* __restrict__ bias,
                                               float* __restrict__ Cext,
                                               int N, int asel, int wsel, int dsel)
{
    extern __shared__ char sm[];
    const uint32_t sbase = smem_u32(sm);
    const int tid = threadIdx.x;
    const int lane = tid & 31, warp = tid >> 5;
    const int wm = warp & 3, wn = warp >> 2;        // 4 x 2 warp grid
    const int rowBase = blockIdx.y * 128, colBase = blockIdx.x * 128;

    const __nv_bfloat16* Ahi = asel ? g_chi : g_xhi;
    const __nv_bfloat16* Alo = asel ? g_clo : g_xlo;
    const __nv_bfloat16 *Bhi, *Blo;
    if (wsel == 0)      { Bhi = g_wqhi; Blo = g_wqlo; }
    else if (wsel == 1) { Bhi = g_wkhi; Blo = g_wklo; }
    else if (wsel == 2) { Bhi = g_wvhi; Blo = g_wvlo; }
    else                { Bhi = g_wohi; Blo = g_wolo; }
    float* C;
    if (dsel == 0) C = g_q; else if (dsel == 1) C = g_k;
    else if (dsel == 2) C = g_v; else C = Cext;

    float acc[2][8][4];
#pragma unroll
    for (int mt = 0; mt < 2; mt++)
#pragma unroll
        for (int nt = 0; nt < 8; nt++)
#pragma unroll
            for (int e = 0; e < 4; e++) acc[mt][nt][e] = 0.f;

    // loader mapping: thread covers rows lr and lr+64, 16B chunk lc
    const int lr = tid >> 2, lc = tid & 3;

    // ldmatrix lane-address components (computed once)
    const int a_r = (lane & 7) + ((lane & 8) ? 8 : 0);      // row within 16
    const uint32_t a_kb = (lane & 16) ? 16 : 0;             // k-byte within 32
    const int b_n = (lane & 7) + ((lane & 16) ? 8 : 0);     // n within 16
    const uint32_t b_kb = (lane & 8) ? 16 : 0;

#define LOAD_STAGE(buf, k0) do { \
    const uint32_t sb_ = sbase + (buf) * STG; \
    _Pragma("unroll") \
    for (int h_ = 0; h_ < 2; h_++) { \
        const int r_ = lr + h_ * 64; \
        const uint32_t so_ = r_ * 80 + lc * 16; \
        const size_t ga_ = (size_t)(rowBase + r_) * DM + (k0) + lc * 8; \
        const size_t gb_ = (size_t)(colBase + r_) * DM + (k0) + lc * 8; \
        CP16(sb_ + OAH + so_, Ahi + ga_); \
        CP16(sb_ + OAL + so_, Alo + ga_); \
        CP16(sb_ + OBH + so_, Bhi + gb_); \
        CP16(sb_ + OBL + so_, Blo + gb_); \
    } \
} while (0)

    LOAD_STAGE(0, 0);
    CP_COMMIT();

    const int ITERS = DM / 32;  // 64
    for (int s = 0; s < ITERS; s++) {
        if (s + 1 < ITERS) { LOAD_STAGE((s + 1) & 1, (s + 1) * 32); CP_COMMIT(); CP_WAIT1(); }
        else               { CP_WAIT0(); }
        __syncthreads();

        const uint32_t sb = sbase + (s & 1) * STG;
#pragma unroll
        for (int ks = 0; ks < 2; ks++) {
            const uint32_t kso = ks * 32;
            uint32_t ah[2][4], al[2][4], bh[8][2], bl[8][2];
#pragma unroll
            for (int mt = 0; mt < 2; mt++) {
                const uint32_t addr = sb + (wm * 32 + mt * 16 + a_r) * 80 + kso + a_kb;
                ldsm_x4(ah[mt][0], ah[mt][1], ah[mt][2], ah[mt][3], addr + OAH);
                ldsm_x4(al[mt][0], al[mt][1], al[mt][2], al[mt][3], addr + OAL);
            }
#pragma unroll
            for (int p = 0; p < 4; p++) {
                const uint32_t addr = sb + (wn * 64 + p * 16 + b_n) * 80 + kso + b_kb;
                uint32_t r0, r1, r2, r3;
                ldsm_x4(r0, r1, r2, r3, addr + OBH);
                bh[p * 2][0] = r0; bh[p * 2][1] = r1;
                bh[p * 2 + 1][0] = r2; bh[p * 2 + 1][1] = r3;
                ldsm_x4(r0, r1, r2, r3, addr + OBL);
                bl[p * 2][0] = r0; bl[p * 2][1] = r1;
                bl[p * 2 + 1][0] = r2; bl[p * 2 + 1][1] = r3;
            }
#pragma unroll
            for (int mt = 0; mt < 2; mt++)
#pragma unroll
                for (int nt = 0; nt < 8; nt++)
                    mma16816(acc[mt][nt], ah[mt], bh[nt]);
#pragma unroll
            for (int mt = 0; mt < 2; mt++)
#pragma unroll
                for (int nt = 0; nt < 8; nt++)
                    mma16816(acc[mt][nt], al[mt], bh[nt]);
#pragma unroll
            for (int mt = 0; mt < 2; mt++)
#pragma unroll
                for (int nt = 0; nt < 8; nt++)
                    mma16816(acc[mt][nt], ah[mt], bl[nt]);
        }
        __syncthreads();
    }

    // epilogue: D frag -> thread (g = lane/4) rows g, g+8; cols t2*2, +1
    const int g = lane >> 2, t2 = lane & 3;
#pragma unroll
    for (int mt = 0; mt < 2; mt++) {
        const int r0 = rowBase + wm * 32 + mt * 16 + g;
#pragma unroll
        for (int nt = 0; nt < 8; nt++) {
            const int col = colBase + wn * 64 + nt * 8 + t2 * 2;
            const float bx = bias[col], by = bias[col + 1];
            float2 o0, o1;
            o0.x = acc[mt][nt][0] + bx; o0.y = acc[mt][nt][1] + by;
            o1.x = acc[mt][nt][2] + bx; o1.y = acc[mt][nt][3] + by;
            *(float2*)(C + (size_t)r0 * N + col) = o0;
            *(float2*)(C + (size_t)(r0 + 8) * N + col) = o1;
        }
    }
}

// ============================================================
// Flash-attention (verified passing kernel, unchanged)
// ============================================================
#define QS 132

__global__ __launch_bounds__(256) void mqa_attn_kernel()
{
    extern __shared__ float sh[];
    float* Qs = sh;
    float* Ks = sh + 64 * QS;
    float* Vs = sh + 2 * 64 * QS;
    float* Ps = sh + 3 * 64 * QS;

    const int qb = blockIdx.x, h = blockIdx.y, b = blockIdx.z;
    const int tid = threadIdx.x;
    const int r = tid >> 2, quad = tid & 3;
    const int t = qb * 64 + r;

    for (int i = tid; i < 64 * 32; i += 256) {
        const int row = i >> 5, c4 = (i & 31) << 2;
        *(float4*)(Qs + row * QS + c4) =
            *(const float4*)(g_q + (size_t)(b * TT + qb * 64 + row) * DM + h * DH + c4);
    }

    float O[32];
#pragma unroll
    for (int u = 0; u < 32; u++) O[u] = 0.f;
    float m_i = -1e30f, l_i = 0.f;
    const float scale = 0.08838834764831845f;

    for (int kb = 0; kb <= qb; kb++) {
        __syncthreads();
        for (int i = tid; i < 64 * 32; i += 256) {
            const int row = i >> 5, c4 = (i & 31) << 2;
            const size_t gidx = (size_t)(b * TT + kb * 64 + row) * DH + c4;
            *(float4*)(Ks + row * QS + c4) = *(const float4*)(g_k + gidx);
            *(float4*)(Vs + row * QS + c4) = *(const float4*)(g_v + gidx);
        }
        __syncthreads();

        float acc[16];
#pragma unroll
        for (int j = 0; j < 16; j++) acc[j] = 0.f;
#pragma unroll 4
        for (int d4 = 0; d4 < 32; d4++) {
            const float4 q4 = *(const float4*)(Qs + r * QS + d4 * 4);
#pragma unroll
            for (int j = 0; j < 16; j++) {
                const float4 k4 = *(const float4*)(Ks + (quad + 4 * j) * QS + d4 * 4);
                acc[j] = fmaf(q4.x, k4.x, fmaf(q4.y, k4.y,
                         fmaf(q4.z, k4.z, fmaf(q4.w, k4.w, acc[j]))));
            }
        }

        float mloc = -1e30f;
        const int sbase = kb * 64 + quad;
#pragma unroll
        for (int j = 0; j < 16; j++) {
            float sv = acc[j] * scale;
            if (sbase + 4 * j > t) sv = -1e30f;
            acc[j] = sv;
            mloc = fmaxf(mloc, sv);
        }
        mloc = fmaxf(mloc, __shfl_xor_sync(0xffffffffu, mloc, 1));
        mloc = fmaxf(mloc, __shfl_xor_sync(0xffffffffu, mloc, 2));
        const float m_new = fmaxf(m_i, mloc);
        const float alpha = __expf(m_i - m_new);

        float psum = 0.f;
#pragma unroll
        for (int j = 0; j < 16; j++) {
            const float p = __expf(acc[j] - m_new);
            psum += p;
            Ps[r * 68 + quad + 4 * j] = p;
        }
        psum += __shfl_xor_sync(0xffffffffu, psum, 1);
        psum += __shfl_xor_sync(0xffffffffu, psum, 2);
        l_i = l_i * alpha + psum;
        m_i = m_new;

#pragma unroll
        for (int u = 0; u < 32; u++) O[u] *= alpha;
        __syncwarp();

#pragma unroll 2
        for (int cc = 0; cc < 64; cc++) {
            const int c = (cc + 17 * quad) & 63;
            const float p = Ps[r * 68 + c];
            const float* vrow = Vs + c * QS + quad * 32;
#pragma unroll
            for (int u4 = 0; u4 < 8; u4++) {
                const float4 v4 = *(const float4*)(vrow + u4 * 4);
                O[u4 * 4 + 0] = fmaf(p, v4.x, O[u4 * 4 + 0]);
                O[u4 * 4 + 1] = fmaf(p, v4.y, O[u4 * 4 + 1]);
                O[u4 * 4 + 2] = fmaf(p, v4.z, O[u4 * 4 + 2]);
                O[u4 * 4 + 3] = fmaf(p, v4.w, O[u4 * 4 + 3]);
            }
        }
    }

    const float inv = 1.0f / l_i;
    float* dst = g_ctx + (size_t)(b * TT + t) * DM + h * DH + quad * 32;
#pragma unroll
    for (int u4 = 0; u4 < 8; u4++) {
        float4 o;
        o.x = O[u4 * 4 + 0] * inv;
        o.y = O[u4 * 4 + 1] * inv;
        o.z = O[u4 * 4 + 2] * inv;
        o.w = O[u4 * 4 + 3] * inv;
        *(float4*)(dst + u4 * 4) = o;
    }
}

// ============================================================
extern "C" void kernel_launch(void* const* d_in, const int* in_sizes, int n_in,
                              void* d_out, int out_size)
{
    const float* x  = (const float*)d_in[0];
    const float* Wq = (const float*)d_in[2];
    const float* bq = (const float*)d_in[3];
    const float* Wk = (const float*)d_in[4];
    const float* bk = (const float*)d_in[5];
    const float* Wv = (const float*)d_in[6];
    const float* bv = (const float*)d_in[7];
    const float* Wo = (const float*)d_in[8];
    const float* bo = (const float*)d_in[9];
    float* out = (float*)d_out;

    const int gsmem = 2 * STG;  // 81920
    cudaFuncSetAttribute(tc_gemm, cudaFuncAttributeMaxDynamicSharedMemorySize, gsmem);
    const int asmem = (3 * 64 * QS + 64 * 68) * (int)sizeof(float);
    cudaFuncSetAttribute(mqa_attn_kernel, cudaFuncAttributeMaxDynamicSharedMemorySize, asmem);

    // weight prep (transpose + bf16 split), x split
    tsplit_kernel<<<dim3(DM / 32, DM / 32), 256>>>(Wq, 0, DM, DM);
    tsplit_kernel<<<dim3(DH / 32, DM / 32), 256>>>(Wk, 1, DM, DH);
    tsplit_kernel<<<dim3(DH / 32, DM / 32), 256>>>(Wv, 2, DM, DH);
    tsplit_kernel<<<dim3(DM / 32, DM / 32), 256>>>(Wo, 3, DM, DM);
    split_kernel<<<4096, 256>>>(x, 0, MROWS * DM / 4);

    // projections (tensor cores)
    tc_gemm<<<dim3(DM / 128, MROWS / 128), 256, gsmem>>>(bq, nullptr, DM, 0, 0, 0);
    tc_gemm<<<dim3(DH / 128, MROWS / 128), 256, gsmem>>>(bk, nullptr, DH, 0, 1, 1);
    tc_gemm<<<dim3(DH / 128, MROWS / 128), 256, gsmem>>>(bv, nullptr, DH, 0, 2, 2);

    // attention
    mqa_attn_kernel<<<dim3(TT / 64, NH, BBAT), 256, asmem>>>();

    // ctx split + output projection
    split_kernel<<<4096, 256>>>(nullptr, 1, MROWS * DM / 4);
    tc_gemm<<<dim3(DM / 128, MROWS / 128), 256, gsmem>>>(bo, out, DM, 1, 3, 3);
}

// round 6
// speedup vs baseline: 3.7318x; 2.7661x over previous
#include <cuda_runtime.h>
#include <cuda_bf16.h>
#include <cstdint>

#define BBAT 4
#define TT 2048
#define DM 2048
#define NH 16
#define DH 128
#define MROWS (BBAT * TT)

// ---- scratch ----
__device__ __nv_bfloat16 g_xhi[(size_t)MROWS * DM], g_xlo[(size_t)MROWS * DM];
__device__ __nv_bfloat16 g_chi[(size_t)MROWS * DM], g_clo[(size_t)MROWS * DM];
__device__ __nv_bfloat16 g_qhi[(size_t)MROWS * DM], g_qlo[(size_t)MROWS * DM];
__device__ __nv_bfloat16 g_khi[(size_t)MROWS * DH], g_klo[(size_t)MROWS * DH];
__device__ __nv_bfloat16 g_vhi[(size_t)MROWS * DH], g_vlo[(size_t)MROWS * DH];
__device__ __nv_bfloat16 g_vthi[(size_t)DH * MROWS], g_vtlo[(size_t)DH * MROWS];
__device__ __nv_bfloat16 g_wqhi[(size_t)DM * DM], g_wqlo[(size_t)DM * DM];
__device__ __nv_bfloat16 g_wkhi[(size_t)DH * DM], g_wklo[(size_t)DH * DM];
__device__ __nv_bfloat16 g_wvhi[(size_t)DH * DM], g_wvlo[(size_t)DH * DM];
__device__ __nv_bfloat16 g_wohi[(size_t)DM * DM], g_wolo[(size_t)DM * DM];

// ---- PTX helpers (sm_80+ classic tensor path) ----
__device__ __forceinline__ uint32_t smem_u32(const void* p) {
    uint32_t a;
    asm("{ .reg .u64 t; cvta.to.shared.u64 t, %1; cvt.u32.u64 %0, t; }" : "=r"(a) : "l"(p));
    return a;
}
#define CP16(s, g) \
    asm volatile("cp.async.cg.shared.global [%0], [%1], 16;" :: "r"(s), "l"(g))
#define CP_COMMIT() asm volatile("cp.async.commit_group;" ::: "memory")
#define CP_WAIT1() asm volatile("cp.async.wait_group 1;" ::: "memory")
#define CP_WAIT0() asm volatile("cp.async.wait_group 0;" ::: "memory")

__device__ __forceinline__ void ldsm_x4(uint32_t& r0, uint32_t& r1, uint32_t& r2,
                                        uint32_t& r3, uint32_t addr) {
    asm volatile("ldmatrix.sync.aligned.m8n8.x4.shared.b16 {%0,%1,%2,%3}, [%4];"
                 : "=r"(r0), "=r"(r1), "=r"(r2), "=r"(r3) : "r"(addr));
}
__device__ __forceinline__ void mma16816(float* c, const uint32_t* a, const uint32_t* b) {
    asm volatile("mma.sync.aligned.m16n8k16.row.col.f32.bf16.bf16.f32 "
                 "{%0,%1,%2,%3}, {%4,%5,%6,%7}, {%8,%9}, {%0,%1,%2,%3};"
                 : "+f"(c[0]), "+f"(c[1]), "+f"(c[2]), "+f"(c[3])
                 : "r"(a[0]), "r"(a[1]), "r"(a[2]), "r"(a[3]), "r"(b[0]), "r"(b[1]));
}

// ---- fp32 -> bf16 hi/lo ----
__device__ __forceinline__ void split1(float v, __nv_bfloat16& h, __nv_bfloat16& l) {
    h = __float2bfloat16(v);
    l = __float2bfloat16(v - __bfloat162float(h));
}
__device__ __forceinline__ uint32_t pk2(__nv_bfloat16 a, __nv_bfloat16 b) {
    return (uint32_t)__bfloat16_as_ushort(a) | ((uint32_t)__bfloat16_as_ushort(b) << 16);
}
__device__ __forceinline__ uint32_t splitpk_hi(float a, float b) {
    return pk2(__float2bfloat16(a), __float2bfloat16(b));
}
__device__ __forceinline__ uint32_t splitpk_lo(float a, float b) {
    __nv_bfloat16 ha = __float2bfloat16(a), hb = __float2bfloat16(b);
    return pk2(__float2bfloat16(a - __bfloat162float(ha)),
               __float2bfloat16(b - __bfloat162float(hb)));
}

__global__ __launch_bounds__(256) void split_kernel(const float* __restrict__ src, int n4) {
    for (int i = blockIdx.x * blockDim.x + threadIdx.x; i < n4; i += gridDim.x * blockDim.x) {
        float4 v = ((const float4*)src)[i];
        __nv_bfloat16 h0, h1, h2, h3, l0, l1, l2, l3;
        split1(v.x, h0, l0); split1(v.y, h1, l1); split1(v.z, h2, l2); split1(v.w, h3, l3);
        uint2 H, L;
        H.x = pk2(h0, h1); H.y = pk2(h2, h3);
        L.x = pk2(l0, l1); L.y = pk2(l2, l3);
        ((uint2*)g_xhi)[i] = H;
        ((uint2*)g_xlo)[i] = L;
    }
}

// transpose W[K,N] -> Wt[N,K] bf16 hi/lo
__global__ __launch_bounds__(256) void tsplit_kernel(const float* __restrict__ W,
                                                     int wsel, int Kd, int Nd) {
    __nv_bfloat16 *hi, *lo;
    if (wsel == 0)      { hi = g_wqhi; lo = g_wqlo; }
    else if (wsel == 1) { hi = g_wkhi; lo = g_wklo; }
    else if (wsel == 2) { hi = g_wvhi; lo = g_wvlo; }
    else                { hi = g_wohi; lo = g_wolo; }
    __shared__ float t[32][33];
    const int nb = blockIdx.x * 32, kb = blockIdx.y * 32;
    const int tx = threadIdx.x & 31, ty = threadIdx.x >> 5;
#pragma unroll
    for (int i = 0; i < 4; i++)
        t[ty + 8 * i][tx] = W[(size_t)(kb + ty + 8 * i) * Nd + nb + tx];
    __syncthreads();
#pragma unroll
    for (int i = 0; i < 4; i++) {
        const int nrow = ty + 8 * i;
        __nv_bfloat16 h, l;
        split1(t[tx][nrow], h, l);
        const size_t o = (size_t)(nb + nrow) * Kd + kb + tx;
        hi[o] = h; lo[o] = l;
    }
}

// transpose V[MROWS][DH] -> Vt[B][DH][T] (both hi and lo)
__global__ __launch_bounds__(256) void vt_kernel() {
    __shared__ __nv_bfloat16 th[32][34], tl[32][34];
    const int b = blockIdx.z, d0 = blockIdx.y * 32, t0 = blockIdx.x * 32;
    const int tx = threadIdx.x & 31, ty = threadIdx.x >> 5;
#pragma unroll
    for (int i = 0; i < 4; i++) {
        const int row = ty + 8 * i;
        const size_t gsrc = (size_t)(b * TT + t0 + row) * DH + d0 + tx;
        th[row][tx] = g_vhi[gsrc];
        tl[row][tx] = g_vlo[gsrc];
    }
    __syncthreads();
#pragma unroll
    for (int i = 0; i < 4; i++) {
        const int drow = ty + 8 * i;
        const size_t gdst = ((size_t)b * DH + d0 + drow) * TT + t0 + tx;
        g_vthi[gdst] = th[tx][drow];
        g_vtlo[gdst] = tl[tx][drow];
    }
}

// ============================================================
// mma.sync bf16x3 GEMM (validated): C = A[.,2048] @ Wt^T + bias
// ============================================================
#define STG 40960
#define OAH 0
#define OAL 10240
#define OBH 20480
#define OBL 30720

__global__ __launch_bounds__(256) void tc_gemm(const float* __restrict__ bias,
                                               float* __restrict__ Cext,
                                               int N, int asel, int wsel, int dsel)
{
    extern __shared__ char sm[];
    const uint32_t sbase = smem_u32(sm);
    const int tid = threadIdx.x;
    const int lane = tid & 31, warp = tid >> 5;
    const int wm = warp & 3, wn = warp >> 2;
    const int rowBase = blockIdx.y * 128, colBase = blockIdx.x * 128;

    const __nv_bfloat16* Ahi = asel ? g_chi : g_xhi;
    const __nv_bfloat16* Alo = asel ? g_clo : g_xlo;
    const __nv_bfloat16 *Bhi, *Blo;
    if (wsel == 0)      { Bhi = g_wqhi; Blo = g_wqlo; }
    else if (wsel == 1) { Bhi = g_wkhi; Blo = g_wklo; }
    else if (wsel == 2) { Bhi = g_wvhi; Blo = g_wvlo; }
    else                { Bhi = g_wohi; Blo = g_wolo; }

    float acc[2][8][4];
#pragma unroll
    for (int mt = 0; mt < 2; mt++)
#pragma unroll
        for (int nt = 0; nt < 8; nt++)
#pragma unroll
            for (int e = 0; e < 4; e++) acc[mt][nt][e] = 0.f;

    const int lr = tid >> 2, lc = tid & 3;
    const int a_r = lane & 15;
    const uint32_t a_kb = (lane & 16) ? 16 : 0;
    const int b_n = (lane & 7) + ((lane & 16) ? 8 : 0);
    const uint32_t b_kb = (lane & 8) ? 16 : 0;

#define LOAD_STAGE(buf, k0) do { \
    const uint32_t sb_ = sbase + (buf) * STG; \
    _Pragma("unroll") \
    for (int h_ = 0; h_ < 2; h_++) { \
        const int r_ = lr + h_ * 64; \
        const uint32_t so_ = r_ * 80 + lc * 16; \
        const size_t ga_ = (size_t)(rowBase + r_) * DM + (k0) + lc * 8; \
        const size_t gb_ = (size_t)(colBase + r_) * DM + (k0) + lc * 8; \
        CP16(sb_ + OAH + so_, Ahi + ga_); \
        CP16(sb_ + OAL + so_, Alo + ga_); \
        CP16(sb_ + OBH + so_, Bhi + gb_); \
        CP16(sb_ + OBL + so_, Blo + gb_); \
    } \
} while (0)

    LOAD_STAGE(0, 0);
    CP_COMMIT();

    const int ITERS = DM / 32;
    for (int s = 0; s < ITERS; s++) {
        if (s + 1 < ITERS) { LOAD_STAGE((s + 1) & 1, (s + 1) * 32); CP_COMMIT(); CP_WAIT1(); }
        else               { CP_WAIT0(); }
        __syncthreads();

        const uint32_t sb = sbase + (s & 1) * STG;
#pragma unroll
        for (int ks = 0; ks < 2; ks++) {
            const uint32_t kso = ks * 32;
            uint32_t ah[2][4], al[2][4], bh[8][2], bl[8][2];
#pragma unroll
            for (int mt = 0; mt < 2; mt++) {
                const uint32_t addr = sb + (wm * 32 + mt * 16 + a_r) * 80 + kso + a_kb;
                ldsm_x4(ah[mt][0], ah[mt][1], ah[mt][2], ah[mt][3], addr + OAH);
                ldsm_x4(al[mt][0], al[mt][1], al[mt][2], al[mt][3], addr + OAL);
            }
#pragma unroll
            for (int p = 0; p < 4; p++) {
                const uint32_t addr = sb + (wn * 64 + p * 16 + b_n) * 80 + kso + b_kb;
                uint32_t r0, r1, r2, r3;
                ldsm_x4(r0, r1, r2, r3, addr + OBH);
                bh[p * 2][0] = r0; bh[p * 2][1] = r1;
                bh[p * 2 + 1][0] = r2; bh[p * 2 + 1][1] = r3;
                ldsm_x4(r0, r1, r2, r3, addr + OBL);
                bl[p * 2][0] = r0; bl[p * 2][1] = r1;
                bl[p * 2 + 1][0] = r2; bl[p * 2 + 1][1] = r3;
            }
#pragma unroll
            for (int mt = 0; mt < 2; mt++)
#pragma unroll
                for (int nt = 0; nt < 8; nt++)
                    mma16816(acc[mt][nt], ah[mt], bh[nt]);
#pragma unroll
            for (int mt = 0; mt < 2; mt++)
#pragma unroll
                for (int nt = 0; nt < 8; nt++)
                    mma16816(acc[mt][nt], al[mt], bh[nt]);
#pragma unroll
            for (int mt = 0; mt < 2; mt++)
#pragma unroll
                for (int nt = 0; nt < 8; nt++)
                    mma16816(acc[mt][nt], ah[mt], bl[nt]);
        }
        __syncthreads();
    }

    const int g = lane >> 2, t2 = lane & 3;
    if (dsel == 3) {
#pragma unroll
        for (int mt = 0; mt < 2; mt++) {
            const int r0 = rowBase + wm * 32 + mt * 16 + g;
#pragma unroll
            for (int nt = 0; nt < 8; nt++) {
                const int col = colBase + wn * 64 + nt * 8 + t2 * 2;
                const float bx = bias[col], by = bias[col + 1];
                float2 o0, o1;
                o0.x = acc[mt][nt][0] + bx; o0.y = acc[mt][nt][1] + by;
                o1.x = acc[mt][nt][2] + bx; o1.y = acc[mt][nt][3] + by;
                *(float2*)(Cext + (size_t)r0 * N + col) = o0;
                *(float2*)(Cext + (size_t)(r0 + 8) * N + col) = o1;
            }
        }
    } else {
        __nv_bfloat16 *Dh, *Dl;
        if (dsel == 0)      { Dh = g_qhi; Dl = g_qlo; }
        else if (dsel == 1) { Dh = g_khi; Dl = g_klo; }
        else                { Dh = g_vhi; Dl = g_vlo; }
#pragma unroll
        for (int mt = 0; mt < 2; mt++) {
            const int r0 = rowBase + wm * 32 + mt * 16 + g;
#pragma unroll
            for (int nt = 0; nt < 8; nt++) {
                const int col = colBase + wn * 64 + nt * 8 + t2 * 2;
                const float bx = bias[col], by = bias[col + 1];
                const float v0 = acc[mt][nt][0] + bx, v1 = acc[mt][nt][1] + by;
                const float v2 = acc[mt][nt][2] + bx, v3 = acc[mt][nt][3] + by;
                *(uint32_t*)&Dh[(size_t)r0 * N + col] = splitpk_hi(v0, v1);
                *(uint32_t*)&Dl[(size_t)r0 * N + col] = splitpk_lo(v0, v1);
                *(uint32_t*)&Dh[(size_t)(r0 + 8) * N + col] = splitpk_hi(v2, v3);
                *(uint32_t*)&Dl[(size_t)(r0 + 8) * N + col] = splitpk_lo(v2, v3);
            }
        }
    }
}

// ============================================================
// Flash attention on mma.sync bf16x3. Per CTA: (qtile 128, h, b).
// 8 warps x 16 q-rows. Key tiles of 64, double-buffered K/Vt.
// smem: Qhi 0, Qlo 34816; stage s @ 69632+s*71680:
//   Khi +0, Klo +17408, Vthi +34816, Vtlo +53248
// ============================================================
#define AQS 272
#define AVS 144
#define OQH 0
#define OQL 34816
#define OKV 69632
#define SKV 71680
#define ASMEM (OKV + 2 * SKV)   // 212992

__global__ __launch_bounds__(256, 1) void attn_mma()
{
    extern __shared__ char sm[];
    const uint32_t sb0 = smem_u32(sm);
    const int qt = blockIdx.x, h = blockIdx.y, b = blockIdx.z;
    const int tid = threadIdx.x, lane = tid & 31, w = tid >> 5;
    const int g = lane >> 2, t2 = lane & 3;
    const int a_r = lane & 15;
    const uint32_t a_kb = (lane & 16) ? 16 : 0;
    const int b_n = (lane & 7) + ((lane & 16) ? 8 : 0);
    const uint32_t b_kb = (lane & 8) ? 16 : 0;

    // Q tile load (group 0)
    {
        const size_t qbase = (size_t)(b * TT + qt * 128) * DM + h * DH;
#pragma unroll
        for (int j = 0; j < 8; j++) {
            const int n = tid + j * 256;
            const int row = n >> 4, ch = n & 15;
            const size_t gq = qbase + (size_t)row * DM + ch * 8;
            CP16(sb0 + OQH + row * AQS + ch * 16, g_qhi + gq);
            CP16(sb0 + OQL + row * AQS + ch * 16, g_qlo + gq);
        }
    }
    CP_COMMIT();

#define LOADKV(buf, kb) do { \
    const uint32_t kvb_ = sb0 + OKV + (buf) * SKV; \
    const size_t kbase_ = (size_t)(b * TT + (kb) * 64) * DH; \
    const size_t vbase_ = (size_t)b * DH * TT + (size_t)(kb) * 64; \
    _Pragma("unroll") \
    for (int j_ = 0; j_ < 4; j_++) { \
        const int n_ = tid + j_ * 256; \
        const int kr_ = n_ >> 4, kc_ = n_ & 15; \
        const size_t gk_ = kbase_ + (size_t)kr_ * DH + kc_ * 8; \
        CP16(kvb_ + kr_ * AQS + kc_ * 16, g_khi + gk_); \
        CP16(kvb_ + 17408 + kr_ * AQS + kc_ * 16, g_klo + gk_); \
        const int vr_ = n_ >> 3, vc_ = n_ & 7; \
        const size_t gv_ = vbase_ + (size_t)vr_ * TT + vc_ * 8; \
        CP16(kvb_ + 34816 + vr_ * AVS + vc_ * 16, g_vthi + gv_); \
        CP16(kvb_ + 53248 + vr_ * AVS + vc_ * 16, g_vtlo + gv_); \
    } \
} while (0)

    const int ntiles = 2 * qt + 2;
    LOADKV(0, 0);
    CP_COMMIT();

    float O[16][4];
#pragma unroll
    for (int i = 0; i < 16; i++)
#pragma unroll
        for (int e = 0; e < 4; e++) O[i][e] = 0.f;
    float m0 = -1e30f, m1 = -1e30f, l0 = 0.f, l1 = 0.f;
    const float scale = 0.08838834764831845f;
    const int qrow0 = qt * 128 + w * 16 + g;   // rows qrow0, qrow0+8

    for (int it = 0; it < ntiles; it++) {
        if (it + 1 < ntiles) { LOADKV((it + 1) & 1, it + 1); CP_COMMIT(); CP_WAIT1(); }
        else                 { CP_WAIT0(); }
        __syncthreads();
        const uint32_t kvb = sb0 + OKV + (it & 1) * SKV;

        // ---- S = Q K^T (x3) ----
        float sS[8][4];
#pragma unroll
        for (int i = 0; i < 8; i++)
#pragma unroll
            for (int e = 0; e < 4; e++) sS[i][e] = 0.f;
#pragma unroll
        for (int kt = 0; kt < 8; kt++) {
            uint32_t ah[4], al[4];
            const uint32_t qaddr = sb0 + (w * 16 + a_r) * AQS + kt * 32 + a_kb;
            ldsm_x4(ah[0], ah[1], ah[2], ah[3], qaddr + OQH);
            ldsm_x4(al[0], al[1], al[2], al[3], qaddr + OQL);
#pragma unroll
            for (int p = 0; p < 4; p++) {
                const uint32_t kaddr = kvb + (p * 16 + b_n) * AQS + kt * 32 + b_kb;
                uint32_t bh0[2], bh1[2], bl0[2], bl1[2];
                ldsm_x4(bh0[0], bh0[1], bh1[0], bh1[1], kaddr);
                ldsm_x4(bl0[0], bl0[1], bl1[0], bl1[1], kaddr + 17408);
                mma16816(sS[2 * p], ah, bh0);
                mma16816(sS[2 * p + 1], ah, bh1);
                mma16816(sS[2 * p], al, bh0);
                mma16816(sS[2 * p + 1], al, bh1);
                mma16816(sS[2 * p], ah, bl0);
                mma16816(sS[2 * p + 1], ah, bl1);
            }
        }

        // ---- softmax (online) ----
        const int kcol0 = it * 64 + 2 * t2;
        float ml0 = -1e30f, ml1 = -1e30f;
#pragma unroll
        for (int nt = 0; nt < 8; nt++) {
            const int c = kcol0 + nt * 8;
            float s0 = sS[nt][0] * scale, s1 = sS[nt][1] * scale;
            float s2 = sS[nt][2] * scale, s3 = sS[nt][3] * scale;
            if (c > qrow0)         s0 = -1e30f;
            if (c + 1 > qrow0)     s1 = -1e30f;
            if (c > qrow0 + 8)     s2 = -1e30f;
            if (c + 1 > qrow0 + 8) s3 = -1e30f;
            sS[nt][0] = s0; sS[nt][1] = s1; sS[nt][2] = s2; sS[nt][3] = s3;
            ml0 = fmaxf(ml0, fmaxf(s0, s1));
            ml1 = fmaxf(ml1, fmaxf(s2, s3));
        }
        ml0 = fmaxf(ml0, __shfl_xor_sync(0xffffffffu, ml0, 1));
        ml0 = fmaxf(ml0, __shfl_xor_sync(0xffffffffu, ml0, 2));
        ml1 = fmaxf(ml1, __shfl_xor_sync(0xffffffffu, ml1, 1));
        ml1 = fmaxf(ml1, __shfl_xor_sync(0xffffffffu, ml1, 2));
        const float mn0 = fmaxf(m0, ml0), mn1 = fmaxf(m1, ml1);
        const float al0 = __expf(m0 - mn0), al1 = __expf(m1 - mn1);

        float ps0 = 0.f, ps1 = 0.f;
        uint32_t aPh[4][4], aPl[4][4];
#pragma unroll
        for (int u = 0; u < 4; u++) {
            const float p00 = __expf(sS[2 * u][0] - mn0);
            const float p01 = __expf(sS[2 * u][1] - mn0);
            const float p02 = __expf(sS[2 * u][2] - mn1);
            const float p03 = __expf(sS[2 * u][3] - mn1);
            const float p10 = __expf(sS[2 * u + 1][0] - mn0);
            const float p11 = __expf(sS[2 * u + 1][1] - mn0);
            const float p12 = __expf(sS[2 * u + 1][2] - mn1);
            const float p13 = __expf(sS[2 * u + 1][3] - mn1);
            ps0 += p00 + p01 + p10 + p11;
            ps1 += p02 + p03 + p12 + p13;
            aPh[u][0] = splitpk_hi(p00, p01); aPl[u][0] = splitpk_lo(p00, p01);
            aPh[u][1] = splitpk_hi(p02, p03); aPl[u][1] = splitpk_lo(p02, p03);
            aPh[u][2] = splitpk_hi(p10, p11); aPl[u][2] = splitpk_lo(p10, p11);
            aPh[u][3] = splitpk_hi(p12, p13); aPl[u][3] = splitpk_lo(p12, p13);
        }
        ps0 += __shfl_xor_sync(0xffffffffu, ps0, 1);
        ps0 += __shfl_xor_sync(0xffffffffu, ps0, 2);
        ps1 += __shfl_xor_sync(0xffffffffu, ps1, 1);
        ps1 += __shfl_xor_sync(0xffffffffu, ps1, 2);
        l0 = l0 * al0 + ps0;
        l1 = l1 * al1 + ps1;
        m0 = mn0; m1 = mn1;
#pragma unroll
        for (int i = 0; i < 16; i++) {
            O[i][0] *= al0; O[i][1] *= al0;
            O[i][2] *= al1; O[i][3] *= al1;
        }

        // ---- O += P V (x3) ----
#pragma unroll
        for (int u = 0; u < 4; u++) {
#pragma unroll
            for (int p = 0; p < 8; p++) {
                const uint32_t vaddr = kvb + 34816 + (p * 16 + b_n) * AVS + u * 32 + b_kb;
                uint32_t bh0[2], bh1[2], bl0[2], bl1[2];
                ldsm_x4(bh0[0], bh0[1], bh1[0], bh1[1], vaddr);
                ldsm_x4(bl0[0], bl0[1], bl1[0], bl1[1], vaddr + 18432);
                mma16816(O[2 * p], aPh[u], bh0);
                mma16816(O[2 * p + 1], aPh[u], bh1);
                mma16816(O[2 * p], aPl[u], bh0);
                mma16816(O[2 * p + 1], aPl[u], bh1);
                mma16816(O[2 * p], aPh[u], bl0);
                mma16816(O[2 * p + 1], aPh[u], bl1);
            }
        }
        __syncthreads();
    }

    // ---- epilogue: ctx = O / l, bf16 hi/lo ----
    const float inv0 = 1.0f / l0, inv1 = 1.0f / l1;
    const size_t obase = (size_t)(b * TT + qrow0) * DM + h * DH;
#pragma unroll
    for (int ntd = 0; ntd < 16; ntd++) {
        const int d = ntd * 8 + 2 * t2;
        const float v0 = O[ntd][0] * inv0, v1 = O[ntd][1] * inv0;
        const float v2 = O[ntd][2] * inv1, v3 = O[ntd][3] * inv1;
        *(uint32_t*)&g_chi[obase + d] = splitpk_hi(v0, v1);
        *(uint32_t*)&g_clo[obase + d] = splitpk_lo(v0, v1);
        *(uint32_t*)&g_chi[obase + 8 * DM + d] = splitpk_hi(v2, v3);
        *(uint32_t*)&g_clo[obase + 8 * DM + d] = splitpk_lo(v2, v3);
    }
}

// ============================================================
extern "C" void kernel_launch(void* const* d_in, const int* in_sizes, int n_in,
                              void* d_out, int out_size)
{
    const float* x  = (const float*)d_in[0];
    const float* Wq = (const float*)d_in[2];
    const float* bq = (const float*)d_in[3];
    const float* Wk = (const float*)d_in[4];
    const float* bk = (const float*)d_in[5];
    const float* Wv = (const float*)d_in[6];
    const float* bv = (const float*)d_in[7];
    const float* Wo = (const float*)d_in[8];
    const float* bo = (const float*)d_in[9];
    float* out = (float*)d_out;

    const int gsmem = 2 * STG;
    cudaFuncSetAttribute(tc_gemm, cudaFuncAttributeMaxDynamicSharedMemorySize, gsmem);
    cudaFuncSetAttribute(attn_mma, cudaFuncAttributeMaxDynamicSharedMemorySize, ASMEM);

    tsplit_kernel<<<dim3(DM / 32, DM / 32), 256>>>(Wq, 0, DM, DM);
    tsplit_kernel<<<dim3(DH / 32, DM / 32), 256>>>(Wk, 1, DM, DH);
    tsplit_kernel<<<dim3(DH / 32, DM / 32), 256>>>(Wv, 2, DM, DH);
    tsplit_kernel<<<dim3(DM / 32, DM / 32), 256>>>(Wo, 3, DM, DM);
    split_kernel<<<4096, 256>>>(x, MROWS * DM / 4);

    tc_gemm<<<dim3(DM / 128, MROWS / 128), 256, gsmem>>>(bq, nullptr, DM, 0, 0, 0);
    tc_gemm<<<dim3(DH / 128, MROWS / 128), 256, gsmem>>>(bk, nullptr, DH, 0, 1, 1);
    tc_gemm<<<dim3(DH / 128, MROWS / 128), 256, gsmem>>>(bv, nullptr, DH, 0, 2, 2);

    vt_kernel<<<dim3(TT / 32, DH / 32, BBAT), 256>>>();

    attn_mma<<<dim3(TT / 128, NH, BBAT), 256, ASMEM>>>();

    tc_gemm<<<dim3(DM / 128, MROWS / 128), 256, gsmem>>>(bo, out, DM, 1, 3, 3);
}

// round 8
// speedup vs baseline: 4.3899x; 1.1764x over previous
#include <cuda_runtime.h>
#include <cuda_bf16.h>
#include <cstdint>

#define BBAT 4
#define TT 2048
#define DM 2048
#define NH 16
#define DH 128
#define MROWS (BBAT * TT)

// ---- scratch ----
__device__ __nv_bfloat16 g_xhi[(size_t)MROWS * DM], g_xlo[(size_t)MROWS * DM];
__device__ __nv_bfloat16 g_chi[(size_t)MROWS * DM], g_clo[(size_t)MROWS * DM];
__device__ __nv_bfloat16 g_qhi[(size_t)MROWS * DM], g_qlo[(size_t)MROWS * DM];
__device__ __nv_bfloat16 g_khi[(size_t)MROWS * DH], g_klo[(size_t)MROWS * DH];
__device__ __nv_bfloat16 g_vhi[(size_t)MROWS * DH], g_vlo[(size_t)MROWS * DH];
__device__ __nv_bfloat16 g_vthi[(size_t)DH * MROWS], g_vtlo[(size_t)DH * MROWS];
__device__ __nv_bfloat16 g_wqhi[(size_t)DM * DM], g_wqlo[(size_t)DM * DM];
__device__ __nv_bfloat16 g_wkhi[(size_t)DH * DM], g_wklo[(size_t)DH * DM];
__device__ __nv_bfloat16 g_wvhi[(size_t)DH * DM], g_wvlo[(size_t)DH * DM];
__device__ __nv_bfloat16 g_wohi[(size_t)DM * DM], g_wolo[(size_t)DM * DM];

// ---- PTX helpers ----
__device__ __forceinline__ uint32_t smem_u32(const void* p) {
    uint32_t a;
    asm("{ .reg .u64 t; cvta.to.shared.u64 t, %1; cvt.u32.u64 %0, t; }" : "=r"(a) : "l"(p));
    return a;
}
#define CP16(s, g) \
    asm volatile("cp.async.cg.shared.global [%0], [%1], 16;" :: "r"(s), "l"(g))
#define CP_COMMIT() asm volatile("cp.async.commit_group;" ::: "memory")
#define CP_WAIT1() asm volatile("cp.async.wait_group 1;" ::: "memory")
#define CP_WAIT0() asm volatile("cp.async.wait_group 0;" ::: "memory")

__device__ __forceinline__ void ldsm_x4(uint32_t& r0, uint32_t& r1, uint32_t& r2,
                                        uint32_t& r3, uint32_t addr) {
    asm volatile("ldmatrix.sync.aligned.m8n8.x4.shared.b16 {%0,%1,%2,%3}, [%4];"
                 : "=r"(r0), "=r"(r1), "=r"(r2), "=r"(r3) : "r"(addr));
}
__device__ __forceinline__ void mma16816(float* c, const uint32_t* a, const uint32_t* b) {
    asm volatile("mma.sync.aligned.m16n8k16.row.col.f32.bf16.bf16.f32 "
                 "{%0,%1,%2,%3}, {%4,%5,%6,%7}, {%8,%9}, {%0,%1,%2,%3};"
                 : "+f"(c[0]), "+f"(c[1]), "+f"(c[2]), "+f"(c[3])
                 : "r"(a[0]), "r"(a[1]), "r"(a[2]), "r"(a[3]), "r"(b[0]), "r"(b[1]));
}

// ---- fp32 -> bf16 hi/lo ----
__device__ __forceinline__ void split1(float v, __nv_bfloat16& h, __nv_bfloat16& l) {
    h = __float2bfloat16(v);
    l = __float2bfloat16(v - __bfloat162float(h));
}
__device__ __forceinline__ uint32_t pk2(__nv_bfloat16 a, __nv_bfloat16 b) {
    return (uint32_t)__bfloat16_as_ushort(a) | ((uint32_t)__bfloat16_as_ushort(b) << 16);
}
__device__ __forceinline__ uint32_t splitpk_hi(float a, float b) {
    return pk2(__float2bfloat16(a), __float2bfloat16(b));
}
__device__ __forceinline__ uint32_t splitpk_lo(float a, float b) {
    __nv_bfloat16 ha = __float2bfloat16(a), hb = __float2bfloat16(b);
    return pk2(__float2bfloat16(a - __bfloat162float(ha)),
               __float2bfloat16(b - __bfloat162float(hb)));
}

__global__ __launch_bounds__(256) void split_kernel(const float* __restrict__ src, int n4) {
    for (int i = blockIdx.x * blockDim.x + threadIdx.x; i < n4; i += gridDim.x * blockDim.x) {
        float4 v = ((const float4*)src)[i];
        __nv_bfloat16 h0, h1, h2, h3, l0, l1, l2, l3;
        split1(v.x, h0, l0); split1(v.y, h1, l1); split1(v.z, h2, l2); split1(v.w, h3, l3);
        uint2 H, L;
        H.x = pk2(h0, h1); H.y = pk2(h2, h3);
        L.x = pk2(l0, l1); L.y = pk2(l2, l3);
        ((uint2*)g_xhi)[i] = H;
        ((uint2*)g_xlo)[i] = L;
    }
}

__global__ __launch_bounds__(256) void tsplit_kernel(const float* __restrict__ W,
                                                     int wsel, int Kd, int Nd) {
    __nv_bfloat16 *hi, *lo;
    if (wsel == 0)      { hi = g_wqhi; lo = g_wqlo; }
    else if (wsel == 1) { hi = g_wkhi; lo = g_wklo; }
    else if (wsel == 2) { hi = g_wvhi; lo = g_wvlo; }
    else                { hi = g_wohi; lo = g_wolo; }
    __shared__ float t[32][33];
    const int nb = blockIdx.x * 32, kb = blockIdx.y * 32;
    const int tx = threadIdx.x & 31, ty = threadIdx.x >> 5;
#pragma unroll
    for (int i = 0; i < 4; i++)
        t[ty + 8 * i][tx] = W[(size_t)(kb + ty + 8 * i) * Nd + nb + tx];
    __syncthreads();
#pragma unroll
    for (int i = 0; i < 4; i++) {
        const int nrow = ty + 8 * i;
        __nv_bfloat16 h, l;
        split1(t[tx][nrow], h, l);
        const size_t o = (size_t)(nb + nrow) * Kd + kb + tx;
        hi[o] = h; lo[o] = l;
    }
}

__global__ __launch_bounds__(256) void vt_kernel() {
    __shared__ __nv_bfloat16 th[32][34], tl[32][34];
    const int b = blockIdx.z, d0 = blockIdx.y * 32, t0 = blockIdx.x * 32;
    const int tx = threadIdx.x & 31, ty = threadIdx.x >> 5;
#pragma unroll
    for (int i = 0; i < 4; i++) {
        const int row = ty + 8 * i;
        const size_t gsrc = (size_t)(b * TT + t0 + row) * DH + d0 + tx;
        th[row][tx] = g_vhi[gsrc];
        tl[row][tx] = g_vlo[gsrc];
    }
    __syncthreads();
#pragma unroll
    for (int i = 0; i < 4; i++) {
        const int drow = ty + 8 * i;
        const size_t gdst = ((size_t)b * DH + d0 + drow) * TT + t0 + tx;
        g_vthi[gdst] = th[tx][drow];
        g_vtlo[gdst] = tl[tx][drow];
    }
}

// ============================================================
// mma.sync bf16x3 GEMM. wsel==4/dsel==4 -> fused K|V projection
// (blockIdx.x picks Wk/Wv and K/V dest). 2 CTAs/SM target.
// ============================================================
#define STG 40960
#define OAH 0
#define OAL 10240
#define OBH 20480
#define OBL 30720

__global__ __launch_bounds__(256, 2) void tc_gemm(
    const float* __restrict__ bias, const float* __restrict__ bias2,
    float* __restrict__ Cext, int N, int asel, int wsel, int dsel)
{
    extern __shared__ char sm[];
    const uint32_t sbase = smem_u32(sm);
    const int tid = threadIdx.x;
    const int lane = tid & 31, warp = tid >> 5;
    const int wm = warp & 3, wn = warp >> 2;
    const int rowBase = blockIdx.y * 128, colBase = blockIdx.x * 128;

    const __nv_bfloat16* Ahi = asel ? g_chi : g_xhi;
    const __nv_bfloat16* Alo = asel ? g_clo : g_xlo;
    const __nv_bfloat16 *Bhi, *Blo;
    if (wsel == 0)      { Bhi = g_wqhi; Blo = g_wqlo; }
    else if (wsel == 3) { Bhi = g_wohi; Blo = g_wolo; }
    else if (wsel == 4) {
        if (blockIdx.x == 0) { Bhi = g_wkhi; Blo = g_wklo; }
        else                 { Bhi = g_wvhi; Blo = g_wvlo; }
    } else              { Bhi = g_wqhi; Blo = g_wqlo; }
    const int wRow0 = (wsel == 4) ? 0 : colBase;

    float acc[2][8][4];
#pragma unroll
    for (int mt = 0; mt < 2; mt++)
#pragma unroll
        for (int nt = 0; nt < 8; nt++)
#pragma unroll
            for (int e = 0; e < 4; e++) acc[mt][nt][e] = 0.f;

    const int lr = tid >> 2, lc = tid & 3;
    const int a_r = lane & 15;
    const uint32_t a_kb = (lane & 16) ? 16 : 0;
    const int b_n = (lane & 7) + ((lane & 16) ? 8 : 0);
    const uint32_t b_kb = (lane & 8) ? 16 : 0;

#define LOAD_STAGE(buf, k0) do { \
    const uint32_t sb_ = sbase + (buf) * STG; \
    _Pragma("unroll") \
    for (int h_ = 0; h_ < 2; h_++) { \
        const int r_ = lr + h_ * 64; \
        const uint32_t so_ = r_ * 80 + lc * 16; \
        const size_t ga_ = (size_t)(rowBase + r_) * DM + (k0) + lc * 8; \
        const size_t gb_ = (size_t)(wRow0 + r_) * DM + (k0) + lc * 8; \
        CP16(sb_ + OAH + so_, Ahi + ga_); \
        CP16(sb_ + OAL + so_, Alo + ga_); \
        CP16(sb_ + OBH + so_, Bhi + gb_); \
        CP16(sb_ + OBL + so_, Blo + gb_); \
    } \
} while (0)

    LOAD_STAGE(0, 0);
    CP_COMMIT();

    const int ITERS = DM / 32;
    for (int s = 0; s < ITERS; s++) {
        if (s + 1 < ITERS) { LOAD_STAGE((s + 1) & 1, (s + 1) * 32); CP_COMMIT(); CP_WAIT1(); }
        else               { CP_WAIT0(); }
        __syncthreads();

        const uint32_t sb = sbase + (s & 1) * STG;
#pragma unroll
        for (int ks = 0; ks < 2; ks++) {
            const uint32_t kso = ks * 32;
            // pass 1: Ah * Bh
            uint32_t ah[2][4], bb[8][2];
#pragma unroll
            for (int mt = 0; mt < 2; mt++) {
                const uint32_t addr = sb + OAH + (wm * 32 + mt * 16 + a_r) * 80 + kso + a_kb;
                ldsm_x4(ah[mt][0], ah[mt][1], ah[mt][2], ah[mt][3], addr);
            }
#pragma unroll
            for (int p = 0; p < 4; p++) {
                const uint32_t addr = sb + OBH + (wn * 64 + p * 16 + b_n) * 80 + kso + b_kb;
                ldsm_x4(bb[p * 2][0], bb[p * 2][1], bb[p * 2 + 1][0], bb[p * 2 + 1][1], addr);
            }
#pragma unroll
            for (int mt = 0; mt < 2; mt++)
#pragma unroll
                for (int nt = 0; nt < 8; nt++)
                    mma16816(acc[mt][nt], ah[mt], bb[nt]);
            // pass 2: Al * Bh
            {
                uint32_t al[2][4];
#pragma unroll
                for (int mt = 0; mt < 2; mt++) {
                    const uint32_t addr = sb + OAL + (wm * 32 + mt * 16 + a_r) * 80 + kso + a_kb;
                    ldsm_x4(al[mt][0], al[mt][1], al[mt][2], al[mt][3], addr);
                }
#pragma unroll
                for (int mt = 0; mt < 2; mt++)
#pragma unroll
                    for (int nt = 0; nt < 8; nt++)
                        mma16816(acc[mt][nt], al[mt], bb[nt]);
            }
            // pass 3: Ah * Bl
#pragma unroll
            for (int p = 0; p < 4; p++) {
                const uint32_t addr = sb + OBL + (wn * 64 + p * 16 + b_n) * 80 + kso + b_kb;
                ldsm_x4(bb[p * 2][0], bb[p * 2][1], bb[p * 2 + 1][0], bb[p * 2 + 1][1], addr);
            }
#pragma unroll
            for (int mt = 0; mt < 2; mt++)
#pragma unroll
                for (int nt = 0; nt < 8; nt++)
                    mma16816(acc[mt][nt], ah[mt], bb[nt]);
        }
        __syncthreads();
    }

    const int g = lane >> 2, t2 = lane & 3;
    if (dsel == 3) {
#pragma unroll
        for (int mt = 0; mt < 2; mt++) {
            const int r0 = rowBase + wm * 32 + mt * 16 + g;
#pragma unroll
            for (int nt = 0; nt < 8; nt++) {
                const int col = colBase + wn * 64 + nt * 8 + t2 * 2;
                const float bx = bias[col], by = bias[col + 1];
                float2 o0, o1;
                o0.x = acc[mt][nt][0] + bx; o0.y = acc[mt][nt][1] + by;
                o1.x = acc[mt][nt][2] + bx; o1.y = acc[mt][nt][3] + by;
                *(float2*)(Cext + (size_t)r0 * N + col) = o0;
                *(float2*)(Cext + (size_t)(r0 + 8) * N + col) = o1;
            }
        }
    } else if (dsel == 4) {
        __nv_bfloat16* Dh = blockIdx.x ? g_vhi : g_khi;
        __nv_bfloat16* Dl = blockIdx.x ? g_vlo : g_klo;
        const float* bb2 = blockIdx.x ? bias2 : bias;
#pragma unroll
        for (int mt = 0; mt < 2; mt++) {
            const int r0 = rowBase + wm * 32 + mt * 16 + g;
#pragma unroll
            for (int nt = 0; nt < 8; nt++) {
                const int col = wn * 64 + nt * 8 + t2 * 2;
                const float bx = bb2[col], by = bb2[col + 1];
                const float v0 = acc[mt][nt][0] + bx, v1 = acc[mt][nt][1] + by;
                const float v2 = acc[mt][nt][2] + bx, v3 = acc[mt][nt][3] + by;
                *(uint32_t*)&Dh[(size_t)r0 * DH + col] = splitpk_hi(v0, v1);
                *(uint32_t*)&Dl[(size_t)r0 * DH + col] = splitpk_lo(v0, v1);
                *(uint32_t*)&Dh[(size_t)(r0 + 8) * DH + col] = splitpk_hi(v2, v3);
                *(uint32_t*)&Dl[(size_t)(r0 + 8) * DH + col] = splitpk_lo(v2, v3);
            }
        }
    } else {
        __nv_bfloat16* Dh = g_qhi;
        __nv_bfloat16* Dl = g_qlo;
#pragma unroll
        for (int mt = 0; mt < 2; mt++) {
            const int r0 = rowBase + wm * 32 + mt * 16 + g;
#pragma unroll
            for (int nt = 0; nt < 8; nt++) {
                const int col = colBase + wn * 64 + nt * 8 + t2 * 2;
                const float bx = bias[col], by = bias[col + 1];
                const float v0 = acc[mt][nt][0] + bx, v1 = acc[mt][nt][1] + by;
                const float v2 = acc[mt][nt][2] + bx, v3 = acc[mt][nt][3] + by;
                *(uint32_t*)&Dh[(size_t)r0 * N + col] = splitpk_hi(v0, v1);
                *(uint32_t*)&Dl[(size_t)r0 * N + col] = splitpk_lo(v0, v1);
                *(uint32_t*)&Dh[(size_t)(r0 + 8) * N + col] = splitpk_hi(v2, v3);
                *(uint32_t*)&Dl[(size_t)(r0 + 8) * N + col] = splitpk_lo(v2, v3);
            }
        }
    }
}

// ============================================================
// Flash attention on mma.sync bf16x3 (validated). qt reversed
// so heavy causal CTAs launch first.
// ============================================================
#define AQS 272
#define AVS 144
#define OQH 0
#define OQL 34816
#define OKV 69632
#define SKV 71680
#define ASMEM (OKV + 2 * SKV)

__global__ __launch_bounds__(256, 1) void attn_mma()
{
    extern __shared__ char sm[];
    const uint32_t sb0 = smem_u32(sm);
    const int qt = gridDim.x - 1 - blockIdx.x;
    const int h = blockIdx.y, b = blockIdx.z;
    const int tid = threadIdx.x, lane = tid & 31, w = tid >> 5;
    const int g = lane >> 2, t2 = lane & 3;
    const int a_r = lane & 15;
    const uint32_t a_kb = (lane & 16) ? 16 : 0;
    const int b_n = (lane & 7) + ((lane & 16) ? 8 : 0);
    const uint32_t b_kb = (lane & 8) ? 16 : 0;

    {
        const size_t qbase = (size_t)(b * TT + qt * 128) * DM + h * DH;
#pragma unroll
        for (int j = 0; j < 8; j++) {
            const int n = tid + j * 256;
            const int row = n >> 4, ch = n & 15;
            const size_t gq = qbase + (size_t)row * DM + ch * 8;
            CP16(sb0 + OQH + row * AQS + ch * 16, g_qhi + gq);
            CP16(sb0 + OQL + row * AQS + ch * 16, g_qlo + gq);
        }
    }
    CP_COMMIT();

#define LOADKV(buf, kb) do { \
    const uint32_t kvb_ = sb0 + OKV + (buf) * SKV; \
    const size_t kbase_ = (size_t)(b * TT + (kb) * 64) * DH; \
    const size_t vbase_ = (size_t)b * DH * TT + (size_t)(kb) * 64; \
    _Pragma("unroll") \
    for (int j_ = 0; j_ < 4; j_++) { \
        const int n_ = tid + j_ * 256; \
        const int kr_ = n_ >> 4, kc_ = n_ & 15; \
        const size_t gk_ = kbase_ + (size_t)kr_ * DH + kc_ * 8; \
        CP16(kvb_ + kr_ * AQS + kc_ * 16, g_khi + gk_); \
        CP16(kvb_ + 17408 + kr_ * AQS + kc_ * 16, g_klo + gk_); \
        const int vr_ = n_ >> 3, vc_ = n_ & 7; \
        const size_t gv_ = vbase_ + (size_t)vr_ * TT + vc_ * 8; \
        CP16(kvb_ + 34816 + vr_ * AVS + vc_ * 16, g_vthi + gv_); \
        CP16(kvb_ + 53248 + vr_ * AVS + vc_ * 16, g_vtlo + gv_); \
    } \
} while (0)

    const int ntiles = 2 * qt + 2;
    LOADKV(0, 0);
    CP_COMMIT();

    float O[16][4];
#pragma unroll
    for (int i = 0; i < 16; i++)
#pragma unroll
        for (int e = 0; e < 4; e++) O[i][e] = 0.f;
    float m0 = -1e30f, m1 = -1e30f, l0 = 0.f, l1 = 0.f;
    const float scale = 0.08838834764831845f;
    const int qrow0 = qt * 128 + w * 16 + g;

    for (int it = 0; it < ntiles; it++) {
        if (it + 1 < ntiles) { LOADKV((it + 1) & 1, it + 1); CP_COMMIT(); CP_WAIT1(); }
        else                 { CP_WAIT0(); }
        __syncthreads();
        const uint32_t kvb = sb0 + OKV + (it & 1) * SKV;

        float sS[8][4];
#pragma unroll
        for (int i = 0; i < 8; i++)
#pragma unroll
            for (int e = 0; e < 4; e++) sS[i][e] = 0.f;
#pragma unroll
        for (int kt = 0; kt < 8; kt++) {
            uint32_t ah[4], al[4];
            const uint32_t qaddr = sb0 + (w * 16 + a_r) * AQS + kt * 32 + a_kb;
            ldsm_x4(ah[0], ah[1], ah[2], ah[3], qaddr + OQH);
            ldsm_x4(al[0], al[1], al[2], al[3], qaddr + OQL);
#pragma unroll
            for (int p = 0; p < 4; p++) {
                const uint32_t kaddr = kvb + (p * 16 + b_n) * AQS + kt * 32 + b_kb;
                uint32_t bh0[2], bh1[2], bl0[2], bl1[2];
                ldsm_x4(bh0[0], bh0[1], bh1[0], bh1[1], kaddr);
                ldsm_x4(bl0[0], bl0[1], bl1[0], bl1[1], kaddr + 17408);
                mma16816(sS[2 * p], ah, bh0);
                mma16816(sS[2 * p + 1], ah, bh1);
                mma16816(sS[2 * p], al, bh0);
                mma16816(sS[2 * p + 1], al, bh1);
                mma16816(sS[2 * p], ah, bl0);
                mma16816(sS[2 * p + 1], ah, bl1);
            }
        }

        const int kcol0 = it * 64 + 2 * t2;
        float ml0 = -1e30f, ml1 = -1e30f;
#pragma unroll
        for (int nt = 0; nt < 8; nt++) {
            const int c = kcol0 + nt * 8;
            float s0 = sS[nt][0] * scale, s1 = sS[nt][1] * scale;
            float s2 = sS[nt][2] * scale, s3 = sS[nt][3] * scale;
            if (c > qrow0)         s0 = -1e30f;
            if (c + 1 > qrow0)     s1 = -1e30f;
            if (c > qrow0 + 8)     s2 = -1e30f;
            if (c + 1 > qrow0 + 8) s3 = -1e30f;
            sS[nt][0] = s0; sS[nt][1] = s1; sS[nt][2] = s2; sS[nt][3] = s3;
            ml0 = fmaxf(ml0, fmaxf(s0, s1));
            ml1 = fmaxf(ml1, fmaxf(s2, s3));
        }
        ml0 = fmaxf(ml0, __shfl_xor_sync(0xffffffffu, ml0, 1));
        ml0 = fmaxf(ml0, __shfl_xor_sync(0xffffffffu, ml0, 2));
        ml1 = fmaxf(ml1, __shfl_xor_sync(0xffffffffu, ml1, 1));
        ml1 = fmaxf(ml1, __shfl_xor_sync(0xffffffffu, ml1, 2));
        const float mn0 = fmaxf(m0, ml0), mn1 = fmaxf(m1, ml1);
        const float al0 = __expf(m0 - mn0), al1 = __expf(m1 - mn1);

        float ps0 = 0.f, ps1 = 0.f;
        uint32_t aPh[4][4], aPl[4][4];
#pragma unroll
        for (int u = 0; u < 4; u++) {
            const float p00 = __expf(sS[2 * u][0] - mn0);
            const float p01 = __expf(sS[2 * u][1] - mn0);
            const float p02 = __expf(sS[2 * u][2] - mn1);
            const float p03 = __expf(sS[2 * u][3] - mn1);
            const float p10 = __expf(sS[2 * u + 1][0] - mn0);
            const float p11 = __expf(sS[2 * u + 1][1] - mn0);
            const float p12 = __expf(sS[2 * u + 1][2] - mn1);
            const float p13 = __expf(sS[2 * u + 1][3] - mn1);
            ps0 += p00 + p01 + p10 + p11;
            ps1 += p02 + p03 + p12 + p13;
            aPh[u][0] = splitpk_hi(p00, p01); aPl[u][0] = splitpk_lo(p00, p01);
            aPh[u][1] = splitpk_hi(p02, p03); aPl[u][1] = splitpk_lo(p02, p03);
            aPh[u][2] = splitpk_hi(p10, p11); aPl[u][2] = splitpk_lo(p10, p11);
            aPh[u][3] = splitpk_hi(p12, p13); aPl[u][3] = splitpk_lo(p12, p13);
        }
        ps0 += __shfl_xor_sync(0xffffffffu, ps0, 1);
        ps0 += __shfl_xor_sync(0xffffffffu, ps0, 2);
        ps1 += __shfl_xor_sync(0xffffffffu, ps1, 1);
        ps1 += __shfl_xor_sync(0xffffffffu, ps1, 2);
        l0 = l0 * al0 + ps0;
        l1 = l1 * al1 + ps1;
        m0 = mn0; m1 = mn1;
#pragma unroll
        for (int i = 0; i < 16; i++) {
            O[i][0] *= al0; O[i][1] *= al0;
            O[i][2] *= al1; O[i][3] *= al1;
        }

#pragma unroll
        for (int u = 0; u < 4; u++) {
#pragma unroll
            for (int p = 0; p < 8; p++) {
                const uint32_t vaddr = kvb + 34816 + (p * 16 + b_n) * AVS + u * 32 + b_kb;
                uint32_t bh0[2], bh1[2], bl0[2], bl1[2];
                ldsm_x4(bh0[0], bh0[1], bh1[0], bh1[1], vaddr);
                ldsm_x4(bl0[0], bl0[1], bl1[0], bl1[1], vaddr + 18432);
                mma16816(O[2 * p], aPh[u], bh0);
                mma16816(O[2 * p + 1], aPh[u], bh1);
                mma16816(O[2 * p], aPl[u], bh0);
                mma16816(O[2 * p + 1], aPl[u], bh1);
                mma16816(O[2 * p], aPh[u], bl0);
                mma16816(O[2 * p + 1], aPh[u], bl1);
            }
        }
        __syncthreads();
    }

    const float inv0 = 1.0f / l0, inv1 = 1.0f / l1;
    const size_t obase = (size_t)(b * TT + qrow0) * DM + h * DH;
#pragma unroll
    for (int ntd = 0; ntd < 16; ntd++) {
        const int d = ntd * 8 + 2 * t2;
        const float v0 = O[ntd][0] * inv0, v1 = O[ntd][1] * inv0;
        const float v2 = O[ntd][2] * inv1, v3 = O[ntd][3] * inv1;
        *(uint32_t*)&g_chi[obase + d] = splitpk_hi(v0, v1);
        *(uint32_t*)&g_clo[obase + d] = splitpk_lo(v0, v1);
        *(uint32_t*)&g_chi[obase + 8 * DM + d] = splitpk_hi(v2, v3);
        *(uint32_t*)&g_clo[obase + 8 * DM + d] = splitpk_lo(v2, v3);
    }
}

// ============================================================
extern "C" void kernel_launch(void* const* d_in, const int* in_sizes, int n_in,
                              void* d_out, int out_size)
{
    const float* x  = (const float*)d_in[0];
    const float* Wq = (const float*)d_in[2];
    const float* bq = (const float*)d_in[3];
    const float* Wk = (const float*)d_in[4];
    const float* bk = (const float*)d_in[5];
    const float* Wv = (const float*)d_in[6];
    const float* bv = (const float*)d_in[7];
    const float* Wo = (const float*)d_in[8];
    const float* bo = (const float*)d_in[9];
    float* out = (float*)d_out;

    const int gsmem = 2 * STG;
    cudaFuncSetAttribute(tc_gemm, cudaFuncAttributeMaxDynamicSharedMemorySize, gsmem);
    cudaFuncSetAttribute(attn_mma, cudaFuncAttributeMaxDynamicSharedMemorySize, ASMEM);

    tsplit_kernel<<<dim3(DM / 32, DM / 32), 256>>>(Wq, 0, DM, DM);
    tsplit_kernel<<<dim3(DH / 32, DM / 32), 256>>>(Wk, 1, DM, DH);
    tsplit_kernel<<<dim3(DH / 32, DM / 32), 256>>>(Wv, 2, DM, DH);
    tsplit_kernel<<<dim3(DM / 32, DM / 32), 256>>>(Wo, 3, DM, DM);
    split_kernel<<<4096, 256>>>(x, MROWS * DM / 4);

    // Q projection + fused K|V projection
    tc_gemm<<<dim3(DM / 128, MROWS / 128), 256, gsmem>>>(bq, nullptr, nullptr, DM, 0, 0, 0);
    tc_gemm<<<dim3(2, MROWS / 128), 256, gsmem>>>(bk, bv, nullptr, DH, 0, 4, 4);

    vt_kernel<<<dim3(TT / 32, DH / 32, BBAT), 256>>>();

    attn_mma<<<dim3(TT / 128, NH, BBAT), 256, ASMEM>>>();

    // FIXED: Cext is the 3rd argument (was swapped with bias2 -> null-store IMA)
    tc_gemm<<<dim3(DM / 128, MROWS / 128), 256, gsmem>>>(bo, nullptr, out, DM, 1, 3, 3);
}

// round 9
// speedup vs baseline: 4.5250x; 1.0308x over previous
#include <cuda_runtime.h>
#include <cuda_bf16.h>
#include <cstdint>

#define BBAT 4
#define TT 2048
#define DM 2048
#define NH 16
#define DH 128
#define MROWS (BBAT * TT)

// ---- scratch ----
__device__ __nv_bfloat16 g_xhi[(size_t)MROWS * DM], g_xlo[(size_t)MROWS * DM];
__device__ __nv_bfloat16 g_chi[(size_t)MROWS * DM], g_clo[(size_t)MROWS * DM];
__device__ __nv_bfloat16 g_qhi[(size_t)MROWS * DM], g_qlo[(size_t)MROWS * DM];
__device__ __nv_bfloat16 g_khi[(size_t)MROWS * DH], g_klo[(size_t)MROWS * DH];
__device__ __nv_bfloat16 g_vhi[(size_t)MROWS * DH], g_vlo[(size_t)MROWS * DH];
__device__ __nv_bfloat16 g_vthi[(size_t)DH * MROWS], g_vtlo[(size_t)DH * MROWS];
__device__ __nv_bfloat16 g_wqhi[(size_t)DM * DM], g_wqlo[(size_t)DM * DM];
__device__ __nv_bfloat16 g_wkhi[(size_t)DH * DM], g_wklo[(size_t)DH * DM];
__device__ __nv_bfloat16 g_wvhi[(size_t)DH * DM], g_wvlo[(size_t)DH * DM];
__device__ __nv_bfloat16 g_wohi[(size_t)DM * DM], g_wolo[(size_t)DM * DM];

// ---- PTX helpers ----
__device__ __forceinline__ uint32_t smem_u32(const void* p) {
    uint32_t a;
    asm("{ .reg .u64 t; cvta.to.shared.u64 t, %1; cvt.u32.u64 %0, t; }" : "=r"(a) : "l"(p));
    return a;
}
#define CP16(s, g) \
    asm volatile("cp.async.cg.shared.global [%0], [%1], 16;" :: "r"(s), "l"(g))
#define CP_COMMIT() asm volatile("cp.async.commit_group;" ::: "memory")
#define CP_WAIT2() asm volatile("cp.async.wait_group 2;" ::: "memory")
#define CP_WAIT1() asm volatile("cp.async.wait_group 1;" ::: "memory")
#define CP_WAIT0() asm volatile("cp.async.wait_group 0;" ::: "memory")

__device__ __forceinline__ void ldsm_x4(uint32_t& r0, uint32_t& r1, uint32_t& r2,
                                        uint32_t& r3, uint32_t addr) {
    asm volatile("ldmatrix.sync.aligned.m8n8.x4.shared.b16 {%0,%1,%2,%3}, [%4];"
                 : "=r"(r0), "=r"(r1), "=r"(r2), "=r"(r3) : "r"(addr));
}
__device__ __forceinline__ void mma16816(float* c, const uint32_t* a, const uint32_t* b) {
    asm volatile("mma.sync.aligned.m16n8k16.row.col.f32.bf16.bf16.f32 "
                 "{%0,%1,%2,%3}, {%4,%5,%6,%7}, {%8,%9}, {%0,%1,%2,%3};"
                 : "+f"(c[0]), "+f"(c[1]), "+f"(c[2]), "+f"(c[3])
                 : "r"(a[0]), "r"(a[1]), "r"(a[2]), "r"(a[3]), "r"(b[0]), "r"(b[1]));
}

// ---- fp32 -> bf16 hi/lo ----
__device__ __forceinline__ void split1(float v, __nv_bfloat16& h, __nv_bfloat16& l) {
    h = __float2bfloat16(v);
    l = __float2bfloat16(v - __bfloat162float(h));
}
__device__ __forceinline__ uint32_t pk2(__nv_bfloat16 a, __nv_bfloat16 b) {
    return (uint32_t)__bfloat16_as_ushort(a) | ((uint32_t)__bfloat16_as_ushort(b) << 16);
}
__device__ __forceinline__ uint32_t splitpk_hi(float a, float b) {
    return pk2(__float2bfloat16(a), __float2bfloat16(b));
}
__device__ __forceinline__ uint32_t splitpk_lo(float a, float b) {
    __nv_bfloat16 ha = __float2bfloat16(a), hb = __float2bfloat16(b);
    return pk2(__float2bfloat16(a - __bfloat162float(ha)),
               __float2bfloat16(b - __bfloat162float(hb)));
}

// ============================================================
// Fused prep: grid segments
//   [0,4096)      x split
//   [4096,8192)   Wq transpose-split
//   [8192,8448)   Wk
//   [8448,8704)   Wv
//   [8704,12800)  Wo
// ============================================================
__device__ __forceinline__ void do_tsplit(const float* __restrict__ W,
                                          __nv_bfloat16* hi, __nv_bfloat16* lo,
                                          int Kd, int Nd, int bx2,
                                          float (*t)[33]) {
    const int xw = Nd / 32;
    const int nb = (bx2 % xw) * 32, kb = (bx2 / xw) * 32;
    const int tx = threadIdx.x & 31, ty = threadIdx.x >> 5;
#pragma unroll
    for (int i = 0; i < 4; i++)
        t[ty + 8 * i][tx] = W[(size_t)(kb + ty + 8 * i) * Nd + nb + tx];
    __syncthreads();
#pragma unroll
    for (int i = 0; i < 4; i++) {
        const int nrow = ty + 8 * i;
        __nv_bfloat16 h, l;
        split1(t[tx][nrow], h, l);
        const size_t o = (size_t)(nb + nrow) * Kd + kb + tx;
        hi[o] = h; lo[o] = l;
    }
}

__global__ __launch_bounds__(256) void prep_kernel(
    const float* __restrict__ x, const float* __restrict__ Wq,
    const float* __restrict__ Wk, const float* __restrict__ Wv,
    const float* __restrict__ Wo)
{
    __shared__ float t[32][33];
    const int bx = blockIdx.x;
    if (bx < 4096) {
        const int n4 = MROWS * DM / 4;
        for (int i = bx * 256 + threadIdx.x; i < n4; i += 4096 * 256) {
            float4 v = ((const float4*)x)[i];
            __nv_bfloat16 h0, h1, h2, h3, l0, l1, l2, l3;
            split1(v.x, h0, l0); split1(v.y, h1, l1);
            split1(v.z, h2, l2); split1(v.w, h3, l3);
            uint2 H, L;
            H.x = pk2(h0, h1); H.y = pk2(h2, h3);
            L.x = pk2(l0, l1); L.y = pk2(l2, l3);
            ((uint2*)g_xhi)[i] = H;
            ((uint2*)g_xlo)[i] = L;
        }
    } else if (bx < 8192) {
        do_tsplit(Wq, g_wqhi, g_wqlo, DM, DM, bx - 4096, t);
    } else if (bx < 8448) {
        do_tsplit(Wk, g_wkhi, g_wklo, DM, DH, bx - 8192, t);
    } else if (bx < 8704) {
        do_tsplit(Wv, g_wvhi, g_wvlo, DM, DH, bx - 8448, t);
    } else {
        do_tsplit(Wo, g_wohi, g_wolo, DM, DM, bx - 8704, t);
    }
}

__global__ __launch_bounds__(256) void vt_kernel() {
    __shared__ __nv_bfloat16 th[32][34], tl[32][34];
    const int b = blockIdx.z, d0 = blockIdx.y * 32, t0 = blockIdx.x * 32;
    const int tx = threadIdx.x & 31, ty = threadIdx.x >> 5;
#pragma unroll
    for (int i = 0; i < 4; i++) {
        const int row = ty + 8 * i;
        const size_t gsrc = (size_t)(b * TT + t0 + row) * DH + d0 + tx;
        th[row][tx] = g_vhi[gsrc];
        tl[row][tx] = g_vlo[gsrc];
    }
    __syncthreads();
#pragma unroll
    for (int i = 0; i < 4; i++) {
        const int drow = ty + 8 * i;
        const size_t gdst = ((size_t)b * DH + d0 + drow) * TT + t0 + tx;
        g_vthi[gdst] = th[tx][drow];
        g_vtlo[gdst] = tl[tx][drow];
    }
}

// ============================================================
// mma.sync bf16x3 GEMM. fused==1: QKV projection in one grid
// (bx<16 -> Q col tiles; bx==16 -> K; bx==17 -> V).
// fused==0: O projection (fp32 out to Cext).
// ============================================================
#define STG 40960
#define OAH 0
#define OAL 10240
#define OBH 20480
#define OBL 30720

__global__ __launch_bounds__(256, 2) void tc_gemm(
    const float* __restrict__ b0, const float* __restrict__ b1,
    const float* __restrict__ b2, float* __restrict__ Cext,
    int asel, int fused)
{
    extern __shared__ char sm[];
    const uint32_t sbase = smem_u32(sm);
    const int tid = threadIdx.x;
    const int lane = tid & 31, warp = tid >> 5;
    const int wm = warp & 3, wn = warp >> 2;
    const int bx = blockIdx.x;
    const int rowBase = blockIdx.y * 128;

    const __nv_bfloat16* Ahi = asel ? g_chi : g_xhi;
    const __nv_bfloat16* Alo = asel ? g_clo : g_xlo;
    const __nv_bfloat16 *Bhi, *Blo;
    int wRow0;
    if (fused) {
        if (bx < 16)       { Bhi = g_wqhi; Blo = g_wqlo; wRow0 = bx * 128; }
        else if (bx == 16) { Bhi = g_wkhi; Blo = g_wklo; wRow0 = 0; }
        else               { Bhi = g_wvhi; Blo = g_wvlo; wRow0 = 0; }
    } else                 { Bhi = g_wohi; Blo = g_wolo; wRow0 = bx * 128; }

    float acc[2][8][4];
#pragma unroll
    for (int mt = 0; mt < 2; mt++)
#pragma unroll
        for (int nt = 0; nt < 8; nt++)
#pragma unroll
            for (int e = 0; e < 4; e++) acc[mt][nt][e] = 0.f;

    const int lr = tid >> 2, lc = tid & 3;
    const int a_r = lane & 15;
    const uint32_t a_kb = (lane & 16) ? 16 : 0;
    const int b_n = (lane & 7) + ((lane & 16) ? 8 : 0);
    const uint32_t b_kb = (lane & 8) ? 16 : 0;

#define LOAD_STAGE(buf, k0) do { \
    const uint32_t sb_ = sbase + (buf) * STG; \
    _Pragma("unroll") \
    for (int h_ = 0; h_ < 2; h_++) { \
        const int r_ = lr + h_ * 64; \
        const uint32_t so_ = r_ * 80 + lc * 16; \
        const size_t ga_ = (size_t)(rowBase + r_) * DM + (k0) + lc * 8; \
        const size_t gb_ = (size_t)(wRow0 + r_) * DM + (k0) + lc * 8; \
        CP16(sb_ + OAH + so_, Ahi + ga_); \
        CP16(sb_ + OAL + so_, Alo + ga_); \
        CP16(sb_ + OBH + so_, Bhi + gb_); \
        CP16(sb_ + OBL + so_, Blo + gb_); \
    } \
} while (0)

    LOAD_STAGE(0, 0);
    CP_COMMIT();

    const int ITERS = DM / 32;
    for (int s = 0; s < ITERS; s++) {
        if (s + 1 < ITERS) { LOAD_STAGE((s + 1) & 1, (s + 1) * 32); CP_COMMIT(); CP_WAIT1(); }
        else               { CP_WAIT0(); }
        __syncthreads();

        const uint32_t sb = sbase + (s & 1) * STG;
#pragma unroll
        for (int ks = 0; ks < 2; ks++) {
            const uint32_t kso = ks * 32;
            uint32_t ah[2][4], bb[8][2];
#pragma unroll
            for (int mt = 0; mt < 2; mt++) {
                const uint32_t addr = sb + OAH + (wm * 32 + mt * 16 + a_r) * 80 + kso + a_kb;
                ldsm_x4(ah[mt][0], ah[mt][1], ah[mt][2], ah[mt][3], addr);
            }
#pragma unroll
            for (int p = 0; p < 4; p++) {
                const uint32_t addr = sb + OBH + (wn * 64 + p * 16 + b_n) * 80 + kso + b_kb;
                ldsm_x4(bb[p * 2][0], bb[p * 2][1], bb[p * 2 + 1][0], bb[p * 2 + 1][1], addr);
            }
#pragma unroll
            for (int mt = 0; mt < 2; mt++)
#pragma unroll
                for (int nt = 0; nt < 8; nt++)
                    mma16816(acc[mt][nt], ah[mt], bb[nt]);
            {
                uint32_t al[2][4];
#pragma unroll
                for (int mt = 0; mt < 2; mt++) {
                    const uint32_t addr = sb + OAL + (wm * 32 + mt * 16 + a_r) * 80 + kso + a_kb;
                    ldsm_x4(al[mt][0], al[mt][1], al[mt][2], al[mt][3], addr);
                }
#pragma unroll
                for (int mt = 0; mt < 2; mt++)
#pragma unroll
                    for (int nt = 0; nt < 8; nt++)
                        mma16816(acc[mt][nt], al[mt], bb[nt]);
            }
#pragma unroll
            for (int p = 0; p < 4; p++) {
                const uint32_t addr = sb + OBL + (wn * 64 + p * 16 + b_n) * 80 + kso + b_kb;
                ldsm_x4(bb[p * 2][0], bb[p * 2][1], bb[p * 2 + 1][0], bb[p * 2 + 1][1], addr);
            }
#pragma unroll
            for (int mt = 0; mt < 2; mt++)
#pragma unroll
                for (int nt = 0; nt < 8; nt++)
                    mma16816(acc[mt][nt], ah[mt], bb[nt]);
        }
        __syncthreads();
    }

    const int g = lane >> 2, t2 = lane & 3;
    if (!fused) {
        // O projection: fp32 out + bias b0, stride DM
#pragma unroll
        for (int mt = 0; mt < 2; mt++) {
            const int r0 = rowBase + wm * 32 + mt * 16 + g;
#pragma unroll
            for (int nt = 0; nt < 8; nt++) {
                const int col = bx * 128 + wn * 64 + nt * 8 + t2 * 2;
                const float bxv = b0[col], byv = b0[col + 1];
                float2 o0, o1;
                o0.x = acc[mt][nt][0] + bxv; o0.y = acc[mt][nt][1] + byv;
                o1.x = acc[mt][nt][2] + bxv; o1.y = acc[mt][nt][3] + byv;
                *(float2*)(Cext + (size_t)r0 * DM + col) = o0;
                *(float2*)(Cext + (size_t)(r0 + 8) * DM + col) = o1;
            }
        }
    } else if (bx < 16) {
        // Q: bf16 split, stride DM, bias b0
#pragma unroll
        for (int mt = 0; mt < 2; mt++) {
            const int r0 = rowBase + wm * 32 + mt * 16 + g;
#pragma unroll
            for (int nt = 0; nt < 8; nt++) {
                const int col = bx * 128 + wn * 64 + nt * 8 + t2 * 2;
                const float bxv = b0[col], byv = b0[col + 1];
                const float v0 = acc[mt][nt][0] + bxv, v1 = acc[mt][nt][1] + byv;
                const float v2 = acc[mt][nt][2] + bxv, v3 = acc[mt][nt][3] + byv;
                *(uint32_t*)&g_qhi[(size_t)r0 * DM + col] = splitpk_hi(v0, v1);
                *(uint32_t*)&g_qlo[(size_t)r0 * DM + col] = splitpk_lo(v0, v1);
                *(uint32_t*)&g_qhi[(size_t)(r0 + 8) * DM + col] = splitpk_hi(v2, v3);
                *(uint32_t*)&g_qlo[(size_t)(r0 + 8) * DM + col] = splitpk_lo(v2, v3);
            }
        }
    } else {
        // K (bx==16, bias b1) or V (bx==17, bias b2): stride DH, local cols
        __nv_bfloat16* Dh = (bx == 16) ? g_khi : g_vhi;
        __nv_bfloat16* Dl = (bx == 16) ? g_klo : g_vlo;
        const float* bb2 = (bx == 16) ? b1 : b2;
#pragma unroll
        for (int mt = 0; mt < 2; mt++) {
            const int r0 = rowBase + wm * 32 + mt * 16 + g;
#pragma unroll
            for (int nt = 0; nt < 8; nt++) {
                const int col = wn * 64 + nt * 8 + t2 * 2;
                const float bxv = bb2[col], byv = bb2[col + 1];
                const float v0 = acc[mt][nt][0] + bxv, v1 = acc[mt][nt][1] + byv;
                const float v2 = acc[mt][nt][2] + bxv, v3 = acc[mt][nt][3] + byv;
                *(uint32_t*)&Dh[(size_t)r0 * DH + col] = splitpk_hi(v0, v1);
                *(uint32_t*)&Dl[(size_t)r0 * DH + col] = splitpk_lo(v0, v1);
                *(uint32_t*)&Dh[(size_t)(r0 + 8) * DH + col] = splitpk_hi(v2, v3);
                *(uint32_t*)&Dl[(size_t)(r0 + 8) * DH + col] = splitpk_lo(v2, v3);
            }
        }
    }
}

// ============================================================
// Flash attention: Q hoisted to register fragments; 3-stage KV
// pipeline (prefetch depth 2). Heavy qt tiles first.
// smem = 3 stages x 71680:
//   Khi +0 (64x272), Klo +17408, Vthi +34816 (128x144), Vtlo +53248
// Q staged transiently in stage0 (QH +0, QL +34816) before hoist.
// ============================================================
#define AQS 272
#define AVS 144
#define SKV 71680
#define ASMEM (3 * SKV)   // 215040

__global__ __launch_bounds__(256, 1) void attn_mma()
{
    extern __shared__ char sm[];
    const uint32_t sb0 = smem_u32(sm);
    const int qt = gridDim.x - 1 - blockIdx.x;
    const int h = blockIdx.y, b = blockIdx.z;
    const int tid = threadIdx.x, lane = tid & 31, w = tid >> 5;
    const int g = lane >> 2, t2 = lane & 3;
    const int a_r = lane & 15;
    const uint32_t a_kb = (lane & 16) ? 16 : 0;
    const int b_n = (lane & 7) + ((lane & 16) ? 8 : 0);
    const uint32_t b_kb = (lane & 8) ? 16 : 0;

    // --- Q load into stage-0 region, then hoist to registers ---
    {
        const size_t qbase = (size_t)(b * TT + qt * 128) * DM + h * DH;
#pragma unroll
        for (int j = 0; j < 8; j++) {
            const int n = tid + j * 256;
            const int row = n >> 4, ch = n & 15;
            const size_t gq = qbase + (size_t)row * DM + ch * 8;
            CP16(sb0 + row * AQS + ch * 16, g_qhi + gq);
            CP16(sb0 + 34816 + row * AQS + ch * 16, g_qlo + gq);
        }
    }
    CP_COMMIT();
    CP_WAIT0();
    __syncthreads();

    uint32_t aQh[8][4], aQl[8][4];
#pragma unroll
    for (int kt = 0; kt < 8; kt++) {
        const uint32_t qaddr = sb0 + (w * 16 + a_r) * AQS + kt * 32 + a_kb;
        ldsm_x4(aQh[kt][0], aQh[kt][1], aQh[kt][2], aQh[kt][3], qaddr);
        ldsm_x4(aQl[kt][0], aQl[kt][1], aQl[kt][2], aQl[kt][3], qaddr + 34816);
    }
    __syncthreads();   // Q consumed; stage 0 free for KV

#define LOADKV(buf, kb) do { \
    const uint32_t kvb_ = sb0 + (buf) * SKV; \
    const size_t kbase_ = (size_t)(b * TT + (kb) * 64) * DH; \
    const size_t vbase_ = (size_t)b * DH * TT + (size_t)(kb) * 64; \
    _Pragma("unroll") \
    for (int j_ = 0; j_ < 4; j_++) { \
        const int n_ = tid + j_ * 256; \
        const int kr_ = n_ >> 4, kc_ = n_ & 15; \
        const size_t gk_ = kbase_ + (size_t)kr_ * DH + kc_ * 8; \
        CP16(kvb_ + kr_ * AQS + kc_ * 16, g_khi + gk_); \
        CP16(kvb_ + 17408 + kr_ * AQS + kc_ * 16, g_klo + gk_); \
        const int vr_ = n_ >> 3, vc_ = n_ & 7; \
        const size_t gv_ = vbase_ + (size_t)vr_ * TT + vc_ * 8; \
        CP16(kvb_ + 34816 + vr_ * AVS + vc_ * 16, g_vthi + gv_); \
        CP16(kvb_ + 53248 + vr_ * AVS + vc_ * 16, g_vtlo + gv_); \
    } \
} while (0)

    const int ntiles = 2 * qt + 2;   // >= 2 always
    LOADKV(0, 0);
    CP_COMMIT();
    LOADKV(1, 1);
    CP_COMMIT();

    float O[16][4];
#pragma unroll
    for (int i = 0; i < 16; i++)
#pragma unroll
        for (int e = 0; e < 4; e++) O[i][e] = 0.f;
    float m0 = -1e30f, m1 = -1e30f, l0 = 0.f, l1 = 0.f;
    const float scale = 0.08838834764831845f;
    const int qrow0 = qt * 128 + w * 16 + g;

    int buf_cur = 0, buf_pf = 2;
    for (int it = 0; it < ntiles; it++) {
        if (it + 2 < ntiles)      { LOADKV(buf_pf, it + 2); CP_COMMIT(); CP_WAIT2(); }
        else if (it + 1 < ntiles) { CP_WAIT1(); }
        else                      { CP_WAIT0(); }
        __syncthreads();
        const uint32_t kvb = sb0 + buf_cur * SKV;

        // ---- S = Q K^T (x3), Q from registers ----
        float sS[8][4];
#pragma unroll
        for (int i = 0; i < 8; i++)
#pragma unroll
            for (int e = 0; e < 4; e++) sS[i][e] = 0.f;
#pragma unroll
        for (int kt = 0; kt < 8; kt++) {
#pragma unroll
            for (int p = 0; p < 4; p++) {
                const uint32_t kaddr = kvb + (p * 16 + b_n) * AQS + kt * 32 + b_kb;
                uint32_t bh0[2], bh1[2], bl0[2], bl1[2];
                ldsm_x4(bh0[0], bh0[1], bh1[0], bh1[1], kaddr);
                ldsm_x4(bl0[0], bl0[1], bl1[0], bl1[1], kaddr + 17408);
                mma16816(sS[2 * p], aQh[kt], bh0);
                mma16816(sS[2 * p + 1], aQh[kt], bh1);
                mma16816(sS[2 * p], aQl[kt], bh0);
                mma16816(sS[2 * p + 1], aQl[kt], bh1);
                mma16816(sS[2 * p], aQh[kt], bl0);
                mma16816(sS[2 * p + 1], aQh[kt], bl1);
            }
        }

        // ---- online softmax ----
        const int kcol0 = it * 64 + 2 * t2;
        float ml0 = -1e30f, ml1 = -1e30f;
#pragma unroll
        for (int nt = 0; nt < 8; nt++) {
            const int c = kcol0 + nt * 8;
            float s0 = sS[nt][0] * scale, s1 = sS[nt][1] * scale;
            float s2 = sS[nt][2] * scale, s3 = sS[nt][3] * scale;
            if (c > qrow0)         s0 = -1e30f;
            if (c + 1 > qrow0)     s1 = -1e30f;
            if (c > qrow0 + 8)     s2 = -1e30f;
            if (c + 1 > qrow0 + 8) s3 = -1e30f;
            sS[nt][0] = s0; sS[nt][1] = s1; sS[nt][2] = s2; sS[nt][3] = s3;
            ml0 = fmaxf(ml0, fmaxf(s0, s1));
            ml1 = fmaxf(ml1, fmaxf(s2, s3));
        }
        ml0 = fmaxf(ml0, __shfl_xor_sync(0xffffffffu, ml0, 1));
        ml0 = fmaxf(ml0, __shfl_xor_sync(0xffffffffu, ml0, 2));
        ml1 = fmaxf(ml1, __shfl_xor_sync(0xffffffffu, ml1, 1));
        ml1 = fmaxf(ml1, __shfl_xor_sync(0xffffffffu, ml1, 2));
        const float mn0 = fmaxf(m0, ml0), mn1 = fmaxf(m1, ml1);
        const float al0 = __expf(m0 - mn0), al1 = __expf(m1 - mn1);

        float ps0 = 0.f, ps1 = 0.f;
        uint32_t aPh[4][4], aPl[4][4];
#pragma unroll
        for (int u = 0; u < 4; u++) {
            const float p00 = __expf(sS[2 * u][0] - mn0);
            const float p01 = __expf(sS[2 * u][1] - mn0);
            const float p02 = __expf(sS[2 * u][2] - mn1);
            const float p03 = __expf(sS[2 * u][3] - mn1);
            const float p10 = __expf(sS[2 * u + 1][0] - mn0);
            const float p11 = __expf(sS[2 * u + 1][1] - mn0);
            const float p12 = __expf(sS[2 * u + 1][2] - mn1);
            const float p13 = __expf(sS[2 * u + 1][3] - mn1);
            ps0 += p00 + p01 + p10 + p11;
            ps1 += p02 + p03 + p12 + p13;
            aPh[u][0] = splitpk_hi(p00, p01); aPl[u][0] = splitpk_lo(p00, p01);
            aPh[u][1] = splitpk_hi(p02, p03); aPl[u][1] = splitpk_lo(p02, p03);
            aPh[u][2] = splitpk_hi(p10, p11); aPl[u][2] = splitpk_lo(p10, p11);
            aPh[u][3] = splitpk_hi(p12, p13); aPl[u][3] = splitpk_lo(p12, p13);
        }
        ps0 += __shfl_xor_sync(0xffffffffu, ps0, 1);
        ps0 += __shfl_xor_sync(0xffffffffu, ps0, 2);
        ps1 += __shfl_xor_sync(0xffffffffu, ps1, 1);
        ps1 += __shfl_xor_sync(0xffffffffu, ps1, 2);
        l0 = l0 * al0 + ps0;
        l1 = l1 * al1 + ps1;
        m0 = mn0; m1 = mn1;
#pragma unroll
        for (int i = 0; i < 16; i++) {
            O[i][0] *= al0; O[i][1] *= al0;
            O[i][2] *= al1; O[i][3] *= al1;
        }

        // ---- O += P V (x3) ----
#pragma unroll
        for (int u = 0; u < 4; u++) {
#pragma unroll
            for (int p = 0; p < 8; p++) {
                const uint32_t vaddr = kvb + 34816 + (p * 16 + b_n) * AVS + u * 32 + b_kb;
                uint32_t bh0[2], bh1[2], bl0[2], bl1[2];
                ldsm_x4(bh0[0], bh0[1], bh1[0], bh1[1], vaddr);
                ldsm_x4(bl0[0], bl0[1], bl1[0], bl1[1], vaddr + 18432);
                mma16816(O[2 * p], aPh[u], bh0);
                mma16816(O[2 * p + 1], aPh[u], bh1);
                mma16816(O[2 * p], aPl[u], bh0);
                mma16816(O[2 * p + 1], aPl[u], bh1);
                mma16816(O[2 * p], aPh[u], bl0);
                mma16816(O[2 * p + 1], aPh[u], bl1);
            }
        }
        __syncthreads();
        buf_cur = (buf_cur == 2) ? 0 : buf_cur + 1;
        buf_pf  = (buf_pf == 2) ? 0 : buf_pf + 1;
    }

    const float inv0 = 1.0f / l0, inv1 = 1.0f / l1;
    const size_t obase = (size_t)(b * TT + qrow0) * DM + h * DH;
#pragma unroll
    for (int ntd = 0; ntd < 16; ntd++) {
        const int d = ntd * 8 + 2 * t2;
        const float v0 = O[ntd][0] * inv0, v1 = O[ntd][1] * inv0;
        const float v2 = O[ntd][2] * inv1, v3 = O[ntd][3] * inv1;
        *(uint32_t*)&g_chi[obase + d] = splitpk_hi(v0, v1);
        *(uint32_t*)&g_clo[obase + d] = splitpk_lo(v0, v1);
        *(uint32_t*)&g_chi[obase + 8 * DM + d] = splitpk_hi(v2, v3);
        *(uint32_t*)&g_clo[obase + 8 * DM + d] = splitpk_lo(v2, v3);
    }
}

// ============================================================
extern "C" void kernel_launch(void* const* d_in, const int* in_sizes, int n_in,
                              void* d_out, int out_size)
{
    const float* x  = (const float*)d_in[0];
    const float* Wq = (const float*)d_in[2];
    const float* bq = (const float*)d_in[3];
    const float* Wk = (const float*)d_in[4];
    const float* bk = (const float*)d_in[5];
    const float* Wv = (const float*)d_in[6];
    const float* bv = (const float*)d_in[7];
    const float* Wo = (const float*)d_in[8];
    const float* bo = (const float*)d_in[9];
    float* out = (float*)d_out;

    const int gsmem = 2 * STG;
    cudaFuncSetAttribute(tc_gemm, cudaFuncAttributeMaxDynamicSharedMemorySize, gsmem);
    cudaFuncSetAttribute(attn_mma, cudaFuncAttributeMaxDynamicSharedMemorySize, ASMEM);

    // fused prep (x split + 4 weight transposes)
    prep_kernel<<<12800, 256>>>(x, Wq, Wk, Wv, Wo);

    // fused Q|K|V projection (one launch, tail-filled grid)
    tc_gemm<<<dim3(18, MROWS / 128), 256, gsmem>>>(bq, bk, bv, nullptr, 0, 1);

    vt_kernel<<<dim3(TT / 32, DH / 32, BBAT), 256>>>();

    attn_mma<<<dim3(TT / 128, NH, BBAT), 256, ASMEM>>>();

    // O projection (fp32 out)
    tc_gemm<<<dim3(16, MROWS / 128), 256, gsmem>>>(bo, nullptr, nullptr, out, 1, 0);
}